// round 1
// baseline (speedup 1.0000x reference)
#include <cuda_runtime.h>
#include <math.h>
#include <stdint.h>

// Problem constants
#define B_    2
#define L_    4096
#define E_    1024
#define NI    2048      // N_INNER
#define NS    128       // N_STATE
#define NH    32        // N_HEAD
#define HD    64        // HEADDIM
#define NCONV 4
#define CH    64        // CHUNK
#define NC    64        // chunks per sequence (L/CHUNK)
#define CD    2304      // CONV_DIM = NI + 2*NS
#define DIN   4384      // 2*NI + 2*NS + NH
#define ROWS  (B_*L_)   // 8192

// ---------------- scratch (device globals; no allocation allowed) ----------
__device__ float g_zx[(size_t)ROWS * DIN];        // in-proj output (z | xBC | dt_raw)
__device__ float g_x [(size_t)ROWS * NI];         // conv+silu x part
__device__ float g_Bm[(size_t)ROWS * NS];         // conv+silu B part
__device__ float g_Cm[(size_t)ROWS * NS];         // conv+silu C part
__device__ float g_dt[(size_t)ROWS * NH];         // softplus(dt_raw + bias)
__device__ float g_G [(size_t)B_ * NC * CH * CH]; // per-chunk C B^T (shared by all heads)
__device__ float g_st[(size_t)B_ * NC * NH * HD * NS]; // chunk states, then prev-states after scan
__device__ float g_asum[B_ * NC * NH];            // per (b,c,h) sum of A*dt over chunk
__device__ float g_yin[(size_t)ROWS * NI];        // pre-gate y (Y_diag + Y_off + x*D)
__device__ float g_yn [(size_t)ROWS * NI];        // post gate+rmsnorm

// ---------------- helpers ----------------
__device__ __forceinline__ float siluf(float x) { return x / (1.f + expf(-x)); }
__device__ __forceinline__ float softplusf(float x) {
    return (x > 20.f) ? x : log1pf(expf(x));
}

// ---------------- 128x128x8 register-tiled SGEMM (row-major A,B,C) ----------
// M multiple of 128, K multiple of 8; N may be ragged (guarded).
__global__ void __launch_bounds__(256) sgemm128(
    const float* __restrict__ A, const float* __restrict__ B, float* __restrict__ C,
    int M, int N, int K)
{
    __shared__ float As[8][128];
    __shared__ float Bs[8][128];
    const int tid = threadIdx.x;
    const int bx = blockIdx.x, by = blockIdx.y;
    const int aRow = tid >> 1;
    const int aCol = (tid & 1) << 2;
    const int bRow = tid >> 5;
    const int bCol = (tid & 31) << 2;
    const int tx = tid & 15, ty = tid >> 4;
    const float* Ab = A + (size_t)(by * 128) * K;
    const int gcol = bx * 128 + bCol;

    float acc[8][8];
#pragma unroll
    for (int i = 0; i < 8; i++)
#pragma unroll
        for (int j = 0; j < 8; j++) acc[i][j] = 0.f;

    for (int k0 = 0; k0 < K; k0 += 8) {
        float4 av = *reinterpret_cast<const float4*>(Ab + (size_t)aRow * K + k0 + aCol);
        As[aCol + 0][aRow] = av.x;
        As[aCol + 1][aRow] = av.y;
        As[aCol + 2][aRow] = av.z;
        As[aCol + 3][aRow] = av.w;
        float4 bv = make_float4(0.f, 0.f, 0.f, 0.f);
        if (gcol < N)
            bv = *reinterpret_cast<const float4*>(B + (size_t)(k0 + bRow) * N + gcol);
        Bs[bRow][bCol + 0] = bv.x;
        Bs[bRow][bCol + 1] = bv.y;
        Bs[bRow][bCol + 2] = bv.z;
        Bs[bRow][bCol + 3] = bv.w;
        __syncthreads();
#pragma unroll
        for (int kk = 0; kk < 8; kk++) {
            float ar[8], br[8];
#pragma unroll
            for (int i = 0; i < 8; i++) ar[i] = As[kk][ty * 8 + i];
#pragma unroll
            for (int j = 0; j < 8; j++) br[j] = Bs[kk][tx * 8 + j];
#pragma unroll
            for (int i = 0; i < 8; i++)
#pragma unroll
                for (int j = 0; j < 8; j++) acc[i][j] += ar[i] * br[j];
        }
        __syncthreads();
    }
#pragma unroll
    for (int i = 0; i < 8; i++) {
        int r = by * 128 + ty * 8 + i;
#pragma unroll
        for (int j = 0; j < 8; j++) {
            int cidx = bx * 128 + tx * 8 + j;
            if (cidx < N) C[(size_t)r * N + cidx] = acc[i][j];
        }
    }
}

// ---------------- dt = softplus(raw + bias) ----------------
__global__ void dt_kernel(const float* __restrict__ dt_bias) {
    int i = blockIdx.x * blockDim.x + threadIdx.x;
    if (i >= ROWS * NH) return;
    int row = i / NH, h = i % NH;
    float x = g_zx[(size_t)row * DIN + (DIN - NH) + h] + dt_bias[h];
    g_dt[i] = softplusf(x);
}

// ---------------- depthwise causal conv width-4 + silu + split -------------
__global__ void conv_kernel(const float* __restrict__ init_conv,
                            const float* __restrict__ conv_w,
                            const float* __restrict__ conv_b)
{
    int d = blockIdx.x * blockDim.x + threadIdx.x;
    if (d >= CD) return;
    int t = blockIdx.y;
    int b = blockIdx.z;
    float acc = conv_b[d];
#pragma unroll
    for (int k = 0; k < 4; k++) {
        int ti = t + k - 3;
        float v;
        if (ti >= 0) v = g_zx[(size_t)(b * L_ + ti) * DIN + NI + d];
        else         v = init_conv[((size_t)b * CD + d) * NCONV + (4 + ti)];
        acc += conv_w[d * 4 + k] * v;
    }
    float o = siluf(acc);
    int row = b * L_ + t;
    if (d < NI)           g_x [(size_t)row * NI + d] = o;
    else if (d < NI + NS) g_Bm[(size_t)row * NS + (d - NI)] = o;
    else                  g_Cm[(size_t)row * NS + (d - NI - NS)] = o;
}

// ---------------- new_conv_state output ----------------
__global__ void convstate_kernel(float* __restrict__ out) {
    int i = blockIdx.x * blockDim.x + threadIdx.x;
    if (i >= B_ * CD * NCONV) return;
    int k = i % NCONV;
    int d = (i / NCONV) % CD;
    int b = i / (NCONV * CD);
    // L >= 4, so the last 4 timesteps of pre-conv xBC
    out[i] = g_zx[(size_t)(b * L_ + (L_ - 4 + k)) * DIN + NI + d];
}

// ---------------- per-chunk Gram matrix G[l][s] = sum_n C[l,n]B[s,n] -------
__global__ void __launch_bounds__(256) gmat_kernel() {
    const int bc = blockIdx.x;           // b*NC + c
    const int b = bc / NC, c = bc % NC;
    const int row0 = b * L_ + c * CH;
    const int tid = threadIdx.x;
    __shared__ float sC[64 * 33];
    __shared__ float sB[64 * 33];
    const int l = tid >> 2;
    const int s0 = (tid & 3) * 16;
    float acc[16];
#pragma unroll
    for (int j = 0; j < 16; j++) acc[j] = 0.f;
    for (int n0 = 0; n0 < NS; n0 += 32) {
        for (int i = tid; i < 64 * 32; i += 256) {
            int r = i >> 5, nn = i & 31;
            sC[r * 33 + nn] = g_Cm[(size_t)(row0 + r) * NS + n0 + nn];
            sB[r * 33 + nn] = g_Bm[(size_t)(row0 + r) * NS + n0 + nn];
        }
        __syncthreads();
        for (int nn = 0; nn < 32; nn++) {
            float cv = sC[l * 33 + nn];
#pragma unroll
            for (int j = 0; j < 16; j++) acc[j] += cv * sB[(s0 + j) * 33 + nn];
        }
        __syncthreads();
    }
    float* Gp = g_G + (size_t)bc * (CH * CH);
#pragma unroll
    for (int j = 0; j < 16; j++) Gp[l * 64 + s0 + j] = acc[j];
}

// ---------------- per-chunk states[p][n] = sum_l B[l,n]*decay[l]*dt[l]*x[l,p]
__global__ void __launch_bounds__(256) states_kernel(const float* __restrict__ A_log) {
    const int h = blockIdx.x, c = blockIdx.y, b = blockIdx.z;
    const int tid = threadIdx.x;
    __shared__ float sdt[64], acs[64], w[64];
    __shared__ float asum_s;
    __shared__ float xs[64][64];
    __shared__ float sB[64][65];
    const int row0 = b * L_ + c * CH;
    if (tid < 64) sdt[tid] = g_dt[(size_t)(row0 + tid) * NH + h];
    __syncthreads();
    if (tid == 0) {
        float A = -expf(A_log[h]);
        float s = 0.f;
        for (int l = 0; l < 64; l++) { s += A * sdt[l]; acs[l] = s; }
        asum_s = s;
        g_asum[(b * NC + c) * NH + h] = s;
    }
    __syncthreads();
    if (tid < 64) w[tid] = expf(asum_s - acs[tid]) * sdt[tid];
    __syncthreads();
    for (int i = tid; i < 64 * 64; i += 256) {
        int l = i >> 6, p = i & 63;
        xs[l][p] = g_x[(size_t)(row0 + l) * NI + h * HD + p] * w[l];
    }
    const int pg = tid >> 5;   // 8 p-groups of 8
    const int ng = tid & 31;   // 32 n-pairs
    float* outp = g_st + (size_t)((b * NC + c) * NH + h) * HD * NS;
    for (int n0 = 0; n0 < NS; n0 += 64) {
        for (int i = tid; i < 64 * 64; i += 256) {
            int l = i >> 6, n = i & 63;
            sB[l][n] = g_Bm[(size_t)(row0 + l) * NS + n0 + n];
        }
        __syncthreads();
        float acc0[8], acc1[8];
#pragma unroll
        for (int i = 0; i < 8; i++) { acc0[i] = 0.f; acc1[i] = 0.f; }
        for (int l = 0; l < 64; l++) {
            float b0 = sB[l][ng * 2 + 0];
            float b1 = sB[l][ng * 2 + 1];
#pragma unroll
            for (int i = 0; i < 8; i++) {
                float xv = xs[l][pg * 8 + i];
                acc0[i] += xv * b0;
                acc1[i] += xv * b1;
            }
        }
#pragma unroll
        for (int i = 0; i < 8; i++) {
            outp[(size_t)(pg * 8 + i) * NS + n0 + ng * 2 + 0] = acc0[i];
            outp[(size_t)(pg * 8 + i) * NS + n0 + ng * 2 + 1] = acc1[i];
        }
        __syncthreads();
    }
}

// ---------------- cross-chunk state scan (in place: slot c becomes prev-state)
__global__ void __launch_bounds__(256) scan_kernel(const float* __restrict__ init_ssm,
                                                   float* __restrict__ final_out)
{
    const int seg = blockIdx.x;          // 8 segments of 1024
    const int h = blockIdx.y, b = blockIdx.z;
    const int tid = threadIdx.x;
    const int e = seg * 1024 + tid * 4;  // element offset within [p][n] (8192)
    const size_t base_bh = (size_t)(b * NH + h) * HD * NS;
    float4 S = *reinterpret_cast<const float4*>(init_ssm + base_bh + e);
    for (int c = 0; c < NC; c++) {
        float dec = expf(g_asum[(b * NC + c) * NH + h]);
        float* ptr = g_st + (size_t)((b * NC + c) * NH + h) * HD * NS + e;
        float4 cs = *reinterpret_cast<float4*>(ptr);
        *reinterpret_cast<float4*>(ptr) = S;   // prev-state for chunk c
        S.x = dec * S.x + cs.x;
        S.y = dec * S.y + cs.y;
        S.z = dec * S.z + cs.z;
        S.w = dec * S.w + cs.w;
    }
    *reinterpret_cast<float4*>(final_out + base_bh + e) = S;
}

// ---------------- Y = (G∘L)@xdt + exp(Acs)*(C @ Sprev^T) + x*D ------------
__global__ void __launch_bounds__(256) y_kernel(const float* __restrict__ A_log,
                                                const float* __restrict__ Dp)
{
    const int h = blockIdx.x, c = blockIdx.y, b = blockIdx.z;
    const int tid = threadIdx.x;
    __shared__ float sh1[64 * 65];
    __shared__ float sh2[64 * 65];
    __shared__ float acs[64], sdt[64];
    const int row0 = b * L_ + c * CH;
    if (tid < 64) sdt[tid] = g_dt[(size_t)(row0 + tid) * NH + h];
    __syncthreads();
    if (tid == 0) {
        float A = -expf(A_log[h]);
        float s = 0.f;
        for (int l = 0; l < 64; l++) { s += A * sdt[l]; acs[l] = s; }
    }
    __syncthreads();
    const int l = tid >> 2;
    const int p0 = (tid & 3) * 16;
    float acc[16];
#pragma unroll
    for (int j = 0; j < 16; j++) acc[j] = 0.f;

    // Y_off: sum_n C[l,n] * Sprev[p,n]  (n tiled by 32)
    const float* Sp = g_st + (size_t)((b * NC + c) * NH + h) * HD * NS;
    for (int n0 = 0; n0 < NS; n0 += 32) {
        for (int i = tid; i < 64 * 32; i += 256) {
            int r = i >> 5, nn = i & 31;
            sh1[r * 33 + nn] = g_Cm[(size_t)(row0 + r) * NS + n0 + nn];
            sh2[r * 33 + nn] = Sp[(size_t)r * NS + n0 + nn];
        }
        __syncthreads();
        for (int nn = 0; nn < 32; nn++) {
            float cv = sh1[l * 33 + nn];
#pragma unroll
            for (int j = 0; j < 16; j++) acc[j] += cv * sh2[(p0 + j) * 33 + nn];
        }
        __syncthreads();
    }
    float eAl = expf(acs[l]);
#pragma unroll
    for (int j = 0; j < 16; j++) acc[j] *= eAl;

    // Y_diag: sum_s (G[l,s]*Lmat[l,s]) * xdt[s,p]
    const float* Gp = g_G + (size_t)(b * NC + c) * (CH * CH);
    for (int i = tid; i < 64 * 64; i += 256) {
        int r = i >> 6, s = i & 63;
        sh1[r * 65 + s] = (s <= r) ? Gp[i] * expf(acs[r] - acs[s]) : 0.f;
        // reuse (r,s) decomposition for xdt: row r = chunk position, col s = p
        sh2[r * 65 + s] = g_x[(size_t)(row0 + r) * NI + h * HD + s] * sdt[r];
    }
    __syncthreads();
    for (int s = 0; s < 64; s++) {
        float gv = sh1[l * 65 + s];
#pragma unroll
        for (int j = 0; j < 16; j++) acc[j] += gv * sh2[s * 65 + p0 + j];
    }
    float Dv = Dp[h];
#pragma unroll
    for (int j = 0; j < 16; j++) {
        size_t idx = (size_t)(row0 + l) * NI + h * HD + p0 + j;
        g_yin[idx] = acc[j] + g_x[idx] * Dv;
    }
}

// ---------------- gate with silu(z), RMSNorm, * norm_w ----------------
__global__ void __launch_bounds__(256) gate_rms_kernel(const float* __restrict__ norm_w) {
    const int row = blockIdx.x;
    const int tid = threadIdx.x;
    const float* zrow = g_zx + (size_t)row * DIN;
    const float* yrow = g_yin + (size_t)row * NI;
    float v[8];
    float ss = 0.f;
#pragma unroll
    for (int i = 0; i < 8; i++) {
        int idx = tid + i * 256;
        float z = zrow[idx];
        float val = yrow[idx] * siluf(z);
        v[i] = val;
        ss += val * val;
    }
    __shared__ float red[256];
    red[tid] = ss;
    __syncthreads();
    for (int s = 128; s > 0; s >>= 1) {
        if (tid < s) red[tid] += red[tid + s];
        __syncthreads();
    }
    float scale = rsqrtf(red[0] / (float)NI + 1e-5f);
#pragma unroll
    for (int i = 0; i < 8; i++) {
        int idx = tid + i * 256;
        g_yn[(size_t)row * NI + idx] = v[i] * scale * norm_w[idx];
    }
}

// ---------------- launch ----------------
static float* symaddr(const void* sym) {
    void* p = nullptr;
    cudaGetSymbolAddress(&p, sym);
    return (float*)p;
}

extern "C" void kernel_launch(void* const* d_in, const int* in_sizes, int n_in,
                              void* d_out, int out_size)
{
    const float* u         = (const float*)d_in[0];
    const float* init_conv = (const float*)d_in[1];
    const float* init_ssm  = (const float*)d_in[2];
    const float* w_in      = (const float*)d_in[3];
    const float* conv_w    = (const float*)d_in[4];
    const float* conv_b    = (const float*)d_in[5];
    const float* dt_bias   = (const float*)d_in[6];
    const float* A_log     = (const float*)d_in[7];
    const float* Dp        = (const float*)d_in[8];
    const float* norm_w    = (const float*)d_in[9];
    const float* w_out     = (const float*)d_in[10];

    float* out       = (float*)d_out;
    float* out_y     = out;                                    // [2,4096,1024]
    float* out_conv  = out + (size_t)ROWS * E_;                // [2,2304,4]
    float* out_final = out_conv + (size_t)B_ * CD * NCONV;     // [2,32,64,128]

    float* pzx = symaddr(g_zx);
    float* pyn = symaddr(g_yn);

    // 1) in-projection: zxbcdt = u @ w_in   [8192,1024]x[1024,4384]
    sgemm128<<<dim3((DIN + 127) / 128, ROWS / 128), 256>>>(u, w_in, pzx, ROWS, DIN, E_);
    // 2) dt = softplus(raw + bias)
    dt_kernel<<<(ROWS * NH + 255) / 256, 256>>>(dt_bias);
    // 3) causal depthwise conv + silu + split into x/B/C
    conv_kernel<<<dim3((CD + 255) / 256, L_, B_), 256>>>(init_conv, conv_w, conv_b);
    // 4) new_conv_state output
    convstate_kernel<<<(B_ * CD * NCONV + 255) / 256, 256>>>(out_conv);
    // 5) per-chunk Gram matrix G = C B^T (head-independent)
    gmat_kernel<<<B_ * NC, 256>>>();
    // 6) per-chunk states
    states_kernel<<<dim3(NH, NC, B_), 256>>>(A_log);
    // 7) cross-chunk scan (writes prev-states in place + final_state out)
    scan_kernel<<<dim3(8, NH, B_), 256>>>(init_ssm, out_final);
    // 8) Y = diag + off + x*D
    y_kernel<<<dim3(NH, NC, B_), 256>>>(A_log, Dp);
    // 9) gate + rmsnorm
    gate_rms_kernel<<<ROWS, 256>>>(norm_w);
    // 10) out-projection: y = yn @ w_out  [8192,2048]x[2048,1024]
    sgemm128<<<dim3(E_ / 128, ROWS / 128), 256>>>(pyn, w_out, out_y, ROWS, E_, NI);
}

// round 2
// speedup vs baseline: 1.0002x; 1.0002x over previous
#include <cuda_runtime.h>
#include <math.h>
#include <stdint.h>

// Problem constants
#define B_    2
#define L_    4096
#define E_    1024
#define NI    2048      // N_INNER
#define NS    128       // N_STATE
#define NH    32        // N_HEAD
#define HD    64        // HEADDIM
#define NCONV 4
#define CH    64        // CHUNK
#define NC    64        // chunks per sequence (L/CHUNK)
#define CD    2304      // CONV_DIM = NI + 2*NS
#define DIN   4384      // 2*NI + 2*NS + NH
#define ROWS  (B_*L_)   // 8192

// ---------------- scratch (device globals; no allocation allowed) ----------
__device__ float g_zx[(size_t)ROWS * DIN];        // in-proj output (z | xBC | dt_raw)
__device__ float g_x [(size_t)ROWS * NI];         // conv+silu x part
__device__ float g_Bm[(size_t)ROWS * NS];         // conv+silu B part
__device__ float g_Cm[(size_t)ROWS * NS];         // conv+silu C part
__device__ float g_dt[(size_t)ROWS * NH];         // softplus(dt_raw + bias)
__device__ float g_G [(size_t)B_ * NC * CH * CH]; // per-chunk C B^T (shared by all heads)
__device__ float g_st[(size_t)B_ * NC * NH * HD * NS]; // chunk states, then prev-states after scan
__device__ float g_asum[B_ * NC * NH];            // per (b,c,h) sum of A*dt over chunk
__device__ float g_yin[(size_t)ROWS * NI];        // pre-gate y (Y_diag + Y_off + x*D)
__device__ float g_yn [(size_t)ROWS * NI];        // post gate+rmsnorm

// ---------------- helpers ----------------
__device__ __forceinline__ float siluf(float x) { return x / (1.f + expf(-x)); }
__device__ __forceinline__ float softplusf(float x) {
    return (x > 20.f) ? x : log1pf(expf(x));
}

// ---------------- 128x128x8 register-tiled SGEMM (row-major A,B,C) ----------
// M multiple of 128, K multiple of 8; N may be ragged (guarded).
__global__ void __launch_bounds__(256) sgemm128(
    const float* __restrict__ A, const float* __restrict__ B, float* __restrict__ C,
    int M, int N, int K)
{
    __shared__ float As[8][128];
    __shared__ float Bs[8][128];
    const int tid = threadIdx.x;
    const int bx = blockIdx.x, by = blockIdx.y;
    const int aRow = tid >> 1;
    const int aCol = (tid & 1) << 2;
    const int bRow = tid >> 5;
    const int bCol = (tid & 31) << 2;
    const int tx = tid & 15, ty = tid >> 4;
    const float* Ab = A + (size_t)(by * 128) * K;
    const int gcol = bx * 128 + bCol;

    float acc[8][8];
#pragma unroll
    for (int i = 0; i < 8; i++)
#pragma unroll
        for (int j = 0; j < 8; j++) acc[i][j] = 0.f;

    for (int k0 = 0; k0 < K; k0 += 8) {
        float4 av = *reinterpret_cast<const float4*>(Ab + (size_t)aRow * K + k0 + aCol);
        As[aCol + 0][aRow] = av.x;
        As[aCol + 1][aRow] = av.y;
        As[aCol + 2][aRow] = av.z;
        As[aCol + 3][aRow] = av.w;
        float4 bv = make_float4(0.f, 0.f, 0.f, 0.f);
        if (gcol < N)
            bv = *reinterpret_cast<const float4*>(B + (size_t)(k0 + bRow) * N + gcol);
        Bs[bRow][bCol + 0] = bv.x;
        Bs[bRow][bCol + 1] = bv.y;
        Bs[bRow][bCol + 2] = bv.z;
        Bs[bRow][bCol + 3] = bv.w;
        __syncthreads();
#pragma unroll
        for (int kk = 0; kk < 8; kk++) {
            float ar[8], br[8];
#pragma unroll
            for (int i = 0; i < 8; i++) ar[i] = As[kk][ty * 8 + i];
#pragma unroll
            for (int j = 0; j < 8; j++) br[j] = Bs[kk][tx * 8 + j];
#pragma unroll
            for (int i = 0; i < 8; i++)
#pragma unroll
                for (int j = 0; j < 8; j++) acc[i][j] += ar[i] * br[j];
        }
        __syncthreads();
    }
#pragma unroll
    for (int i = 0; i < 8; i++) {
        int r = by * 128 + ty * 8 + i;
#pragma unroll
        for (int j = 0; j < 8; j++) {
            int cidx = bx * 128 + tx * 8 + j;
            if (cidx < N) C[(size_t)r * N + cidx] = acc[i][j];
        }
    }
}

// ---------------- dt = softplus(raw + bias) ----------------
__global__ void dt_kernel(const float* __restrict__ dt_bias) {
    int i = blockIdx.x * blockDim.x + threadIdx.x;
    if (i >= ROWS * NH) return;
    int row = i / NH, h = i % NH;
    float x = g_zx[(size_t)row * DIN + (DIN - NH) + h] + dt_bias[h];
    g_dt[i] = softplusf(x);
}

// ---------------- depthwise causal conv width-4 + silu + split -------------
__global__ void conv_kernel(const float* __restrict__ init_conv,
                            const float* __restrict__ conv_w,
                            const float* __restrict__ conv_b)
{
    int d = blockIdx.x * blockDim.x + threadIdx.x;
    if (d >= CD) return;
    int t = blockIdx.y;
    int b = blockIdx.z;
    float acc = conv_b[d];
#pragma unroll
    for (int k = 0; k < 4; k++) {
        int ti = t + k - 3;
        float v;
        if (ti >= 0) v = g_zx[(size_t)(b * L_ + ti) * DIN + NI + d];
        else         v = init_conv[((size_t)b * CD + d) * NCONV + (4 + ti)];
        acc += conv_w[d * 4 + k] * v;
    }
    float o = siluf(acc);
    int row = b * L_ + t;
    if (d < NI)           g_x [(size_t)row * NI + d] = o;
    else if (d < NI + NS) g_Bm[(size_t)row * NS + (d - NI)] = o;
    else                  g_Cm[(size_t)row * NS + (d - NI - NS)] = o;
}

// ---------------- new_conv_state output ----------------
__global__ void convstate_kernel(float* __restrict__ out) {
    int i = blockIdx.x * blockDim.x + threadIdx.x;
    if (i >= B_ * CD * NCONV) return;
    int k = i % NCONV;
    int d = (i / NCONV) % CD;
    int b = i / (NCONV * CD);
    // L >= 4, so the last 4 timesteps of pre-conv xBC
    out[i] = g_zx[(size_t)(b * L_ + (L_ - 4 + k)) * DIN + NI + d];
}

// ---------------- per-chunk Gram matrix G[l][s] = sum_n C[l,n]B[s,n] -------
__global__ void __launch_bounds__(256) gmat_kernel() {
    const int bc = blockIdx.x;           // b*NC + c
    const int b = bc / NC, c = bc % NC;
    const int row0 = b * L_ + c * CH;
    const int tid = threadIdx.x;
    __shared__ float sC[64 * 33];
    __shared__ float sB[64 * 33];
    const int l = tid >> 2;
    const int s0 = (tid & 3) * 16;
    float acc[16];
#pragma unroll
    for (int j = 0; j < 16; j++) acc[j] = 0.f;
    for (int n0 = 0; n0 < NS; n0 += 32) {
        for (int i = tid; i < 64 * 32; i += 256) {
            int r = i >> 5, nn = i & 31;
            sC[r * 33 + nn] = g_Cm[(size_t)(row0 + r) * NS + n0 + nn];
            sB[r * 33 + nn] = g_Bm[(size_t)(row0 + r) * NS + n0 + nn];
        }
        __syncthreads();
        for (int nn = 0; nn < 32; nn++) {
            float cv = sC[l * 33 + nn];
#pragma unroll
            for (int j = 0; j < 16; j++) acc[j] += cv * sB[(s0 + j) * 33 + nn];
        }
        __syncthreads();
    }
    float* Gp = g_G + (size_t)bc * (CH * CH);
#pragma unroll
    for (int j = 0; j < 16; j++) Gp[l * 64 + s0 + j] = acc[j];
}

// ---------------- per-chunk states[p][n] = sum_l B[l,n]*decay[l]*dt[l]*x[l,p]
__global__ void __launch_bounds__(256) states_kernel(const float* __restrict__ A_log) {
    const int h = blockIdx.x, c = blockIdx.y, b = blockIdx.z;
    const int tid = threadIdx.x;
    __shared__ float sdt[64], acs[64], w[64];
    __shared__ float asum_s;
    __shared__ float xs[64][64];
    __shared__ float sB[64][65];
    const int row0 = b * L_ + c * CH;
    if (tid < 64) sdt[tid] = g_dt[(size_t)(row0 + tid) * NH + h];
    __syncthreads();
    if (tid == 0) {
        float A = -expf(A_log[h]);
        float s = 0.f;
        for (int l = 0; l < 64; l++) { s += A * sdt[l]; acs[l] = s; }
        asum_s = s;
        g_asum[(b * NC + c) * NH + h] = s;
    }
    __syncthreads();
    if (tid < 64) w[tid] = expf(asum_s - acs[tid]) * sdt[tid];
    __syncthreads();
    for (int i = tid; i < 64 * 64; i += 256) {
        int l = i >> 6, p = i & 63;
        xs[l][p] = g_x[(size_t)(row0 + l) * NI + h * HD + p] * w[l];
    }
    const int pg = tid >> 5;   // 8 p-groups of 8
    const int ng = tid & 31;   // 32 n-pairs
    float* outp = g_st + (size_t)((b * NC + c) * NH + h) * HD * NS;
    for (int n0 = 0; n0 < NS; n0 += 64) {
        for (int i = tid; i < 64 * 64; i += 256) {
            int l = i >> 6, n = i & 63;
            sB[l][n] = g_Bm[(size_t)(row0 + l) * NS + n0 + n];
        }
        __syncthreads();
        float acc0[8], acc1[8];
#pragma unroll
        for (int i = 0; i < 8; i++) { acc0[i] = 0.f; acc1[i] = 0.f; }
        for (int l = 0; l < 64; l++) {
            float b0 = sB[l][ng * 2 + 0];
            float b1 = sB[l][ng * 2 + 1];
#pragma unroll
            for (int i = 0; i < 8; i++) {
                float xv = xs[l][pg * 8 + i];
                acc0[i] += xv * b0;
                acc1[i] += xv * b1;
            }
        }
#pragma unroll
        for (int i = 0; i < 8; i++) {
            outp[(size_t)(pg * 8 + i) * NS + n0 + ng * 2 + 0] = acc0[i];
            outp[(size_t)(pg * 8 + i) * NS + n0 + ng * 2 + 1] = acc1[i];
        }
        __syncthreads();
    }
}

// ---------------- cross-chunk state scan (in place: slot c becomes prev-state)
__global__ void __launch_bounds__(256) scan_kernel(const float* __restrict__ init_ssm,
                                                   float* __restrict__ final_out)
{
    const int seg = blockIdx.x;          // 8 segments of 1024
    const int h = blockIdx.y, b = blockIdx.z;
    const int tid = threadIdx.x;
    const int e = seg * 1024 + tid * 4;  // element offset within [p][n] (8192)
    const size_t base_bh = (size_t)(b * NH + h) * HD * NS;
    float4 S = *reinterpret_cast<const float4*>(init_ssm + base_bh + e);
    for (int c = 0; c < NC; c++) {
        float dec = expf(g_asum[(b * NC + c) * NH + h]);
        float* ptr = g_st + (size_t)((b * NC + c) * NH + h) * HD * NS + e;
        float4 cs = *reinterpret_cast<float4*>(ptr);
        *reinterpret_cast<float4*>(ptr) = S;   // prev-state for chunk c
        S.x = dec * S.x + cs.x;
        S.y = dec * S.y + cs.y;
        S.z = dec * S.z + cs.z;
        S.w = dec * S.w + cs.w;
    }
    *reinterpret_cast<float4*>(final_out + base_bh + e) = S;
}

// ---------------- Y = (G∘L)@xdt + exp(Acs)*(C @ Sprev^T) + x*D ------------
__global__ void __launch_bounds__(256) y_kernel(const float* __restrict__ A_log,
                                                const float* __restrict__ Dp)
{
    const int h = blockIdx.x, c = blockIdx.y, b = blockIdx.z;
    const int tid = threadIdx.x;
    __shared__ float sh1[64 * 65];
    __shared__ float sh2[64 * 65];
    __shared__ float acs[64], sdt[64];
    const int row0 = b * L_ + c * CH;
    if (tid < 64) sdt[tid] = g_dt[(size_t)(row0 + tid) * NH + h];
    __syncthreads();
    if (tid == 0) {
        float A = -expf(A_log[h]);
        float s = 0.f;
        for (int l = 0; l < 64; l++) { s += A * sdt[l]; acs[l] = s; }
    }
    __syncthreads();
    const int l = tid >> 2;
    const int p0 = (tid & 3) * 16;
    float acc[16];
#pragma unroll
    for (int j = 0; j < 16; j++) acc[j] = 0.f;

    // Y_off: sum_n C[l,n] * Sprev[p,n]  (n tiled by 32)
    const float* Sp = g_st + (size_t)((b * NC + c) * NH + h) * HD * NS;
    for (int n0 = 0; n0 < NS; n0 += 32) {
        for (int i = tid; i < 64 * 32; i += 256) {
            int r = i >> 5, nn = i & 31;
            sh1[r * 33 + nn] = g_Cm[(size_t)(row0 + r) * NS + n0 + nn];
            sh2[r * 33 + nn] = Sp[(size_t)r * NS + n0 + nn];
        }
        __syncthreads();
        for (int nn = 0; nn < 32; nn++) {
            float cv = sh1[l * 33 + nn];
#pragma unroll
            for (int j = 0; j < 16; j++) acc[j] += cv * sh2[(p0 + j) * 33 + nn];
        }
        __syncthreads();
    }
    float eAl = expf(acs[l]);
#pragma unroll
    for (int j = 0; j < 16; j++) acc[j] *= eAl;

    // Y_diag: sum_s (G[l,s]*Lmat[l,s]) * xdt[s,p]
    const float* Gp = g_G + (size_t)(b * NC + c) * (CH * CH);
    for (int i = tid; i < 64 * 64; i += 256) {
        int r = i >> 6, s = i & 63;
        sh1[r * 65 + s] = (s <= r) ? Gp[i] * expf(acs[r] - acs[s]) : 0.f;
        // reuse (r,s) decomposition for xdt: row r = chunk position, col s = p
        sh2[r * 65 + s] = g_x[(size_t)(row0 + r) * NI + h * HD + s] * sdt[r];
    }
    __syncthreads();
    for (int s = 0; s < 64; s++) {
        float gv = sh1[l * 65 + s];
#pragma unroll
        for (int j = 0; j < 16; j++) acc[j] += gv * sh2[s * 65 + p0 + j];
    }
    float Dv = Dp[h];
#pragma unroll
    for (int j = 0; j < 16; j++) {
        size_t idx = (size_t)(row0 + l) * NI + h * HD + p0 + j;
        g_yin[idx] = acc[j] + g_x[idx] * Dv;
    }
}

// ---------------- gate with silu(z), RMSNorm, * norm_w ----------------
__global__ void __launch_bounds__(256) gate_rms_kernel(const float* __restrict__ norm_w) {
    const int row = blockIdx.x;
    const int tid = threadIdx.x;
    const float* zrow = g_zx + (size_t)row * DIN;
    const float* yrow = g_yin + (size_t)row * NI;
    float v[8];
    float ss = 0.f;
#pragma unroll
    for (int i = 0; i < 8; i++) {
        int idx = tid + i * 256;
        float z = zrow[idx];
        float val = yrow[idx] * siluf(z);
        v[i] = val;
        ss += val * val;
    }
    __shared__ float red[256];
    red[tid] = ss;
    __syncthreads();
    for (int s = 128; s > 0; s >>= 1) {
        if (tid < s) red[tid] += red[tid + s];
        __syncthreads();
    }
    float scale = rsqrtf(red[0] / (float)NI + 1e-5f);
#pragma unroll
    for (int i = 0; i < 8; i++) {
        int idx = tid + i * 256;
        g_yn[(size_t)row * NI + idx] = v[i] * scale * norm_w[idx];
    }
}

// ---------------- launch ----------------
static float* symaddr(const void* sym) {
    void* p = nullptr;
    cudaGetSymbolAddress(&p, sym);
    return (float*)p;
}

extern "C" void kernel_launch(void* const* d_in, const int* in_sizes, int n_in,
                              void* d_out, int out_size)
{
    const float* u         = (const float*)d_in[0];
    const float* init_conv = (const float*)d_in[1];
    const float* init_ssm  = (const float*)d_in[2];
    const float* w_in      = (const float*)d_in[3];
    const float* conv_w    = (const float*)d_in[4];
    const float* conv_b    = (const float*)d_in[5];
    const float* dt_bias   = (const float*)d_in[6];
    const float* A_log     = (const float*)d_in[7];
    const float* Dp        = (const float*)d_in[8];
    const float* norm_w    = (const float*)d_in[9];
    const float* w_out     = (const float*)d_in[10];

    float* out       = (float*)d_out;
    float* out_y     = out;                                    // [2,4096,1024]
    float* out_conv  = out + (size_t)ROWS * E_;                // [2,2304,4]
    float* out_final = out_conv + (size_t)B_ * CD * NCONV;     // [2,32,64,128]

    float* pzx = symaddr(g_zx);
    float* pyn = symaddr(g_yn);

    // 1) in-projection: zxbcdt = u @ w_in   [8192,1024]x[1024,4384]
    sgemm128<<<dim3((DIN + 127) / 128, ROWS / 128), 256>>>(u, w_in, pzx, ROWS, DIN, E_);
    // 2) dt = softplus(raw + bias)
    dt_kernel<<<(ROWS * NH + 255) / 256, 256>>>(dt_bias);
    // 3) causal depthwise conv + silu + split into x/B/C
    conv_kernel<<<dim3((CD + 255) / 256, L_, B_), 256>>>(init_conv, conv_w, conv_b);
    // 4) new_conv_state output
    convstate_kernel<<<(B_ * CD * NCONV + 255) / 256, 256>>>(out_conv);
    // 5) per-chunk Gram matrix G = C B^T (head-independent)
    gmat_kernel<<<B_ * NC, 256>>>();
    // 6) per-chunk states
    states_kernel<<<dim3(NH, NC, B_), 256>>>(A_log);
    // 7) cross-chunk scan (writes prev-states in place + final_state out)
    scan_kernel<<<dim3(8, NH, B_), 256>>>(init_ssm, out_final);
    // 8) Y = diag + off + x*D
    y_kernel<<<dim3(NH, NC, B_), 256>>>(A_log, Dp);
    // 9) gate + rmsnorm
    gate_rms_kernel<<<ROWS, 256>>>(norm_w);
    // 10) out-projection: y = yn @ w_out  [8192,2048]x[2048,1024]
    sgemm128<<<dim3(E_ / 128, ROWS / 128), 256>>>(pyn, w_out, out_y, ROWS, E_, NI);
}

// round 4
// speedup vs baseline: 1.4659x; 1.4656x over previous
#include <cuda_runtime.h>
#include <cuda_bf16.h>
#include <math.h>
#include <stdint.h>

// Problem constants
#define B_    2
#define L_    4096
#define E_    1024
#define NI    2048      // N_INNER
#define NS    128       // N_STATE
#define NH    32        // N_HEAD
#define HD    64        // HEADDIM
#define NCONV 4
#define CH    64        // CHUNK
#define NC    64        // chunks per sequence (L/CHUNK)
#define CD    2304      // CONV_DIM = NI + 2*NS
#define DIN   4384      // 2*NI + 2*NS + NH
#define ROWS  (B_*L_)   // 8192

// ---------------- scratch (device globals; no allocation allowed) ----------
__device__ float g_zx[(size_t)ROWS * DIN];
__device__ float g_x [(size_t)ROWS * NI];
__device__ float g_Bm[(size_t)ROWS * NS];
__device__ float g_Cm[(size_t)ROWS * NS];
__device__ float g_dt[(size_t)ROWS * NH];
__device__ float g_G [(size_t)B_ * NC * CH * CH];
__device__ float g_st[(size_t)B_ * NC * NH * HD * NS];
__device__ float g_asum[B_ * NC * NH];
__device__ float g_yin[(size_t)ROWS * NI];
__device__ float g_yn [(size_t)ROWS * NI];

// ---------------- small helpers ----------------
__device__ __forceinline__ float siluf(float x) { return x / (1.f + expf(-x)); }
__device__ __forceinline__ float softplusf(float x) {
    return (x > 20.f) ? x : log1pf(expf(x));
}
__device__ __forceinline__ uint32_t smem_u32(const void* p) {
    uint32_t a;
    asm("{ .reg .u64 t; cvta.to.shared.u64 t, %1; cvt.u32.u64 %0, t; }" : "=r"(a) : "l"(p));
    return a;
}

// convert 8 fp32 -> 8 bf16 hi (uint4) + 8 bf16 lo (uint4)
__device__ __forceinline__ void cvt8_hilo(const float* f, uint4& hi, uint4& lo) {
    uint32_t h[4], l[4];
#pragma unroll
    for (int i = 0; i < 4; i++) {
        __nv_bfloat16 h0 = __float2bfloat16_rn(f[2*i]);
        __nv_bfloat16 h1 = __float2bfloat16_rn(f[2*i+1]);
        float l0f = f[2*i]   - __bfloat162float(h0);
        float l1f = f[2*i+1] - __bfloat162float(h1);
        __nv_bfloat16 l0 = __float2bfloat16_rn(l0f);
        __nv_bfloat16 l1 = __float2bfloat16_rn(l1f);
        h[i] = (uint32_t)__bfloat16_as_ushort(h0) | ((uint32_t)__bfloat16_as_ushort(h1) << 16);
        l[i] = (uint32_t)__bfloat16_as_ushort(l0) | ((uint32_t)__bfloat16_as_ushort(l1) << 16);
    }
    hi = make_uint4(h[0], h[1], h[2], h[3]);
    lo = make_uint4(l[0], l[1], l[2], l[3]);
}

// ---------------- warp-MMA primitives (sm_80+, valid on base sm_100) -------
__device__ __forceinline__ void ldm_x4(uint32_t* r, uint32_t addr) {
    asm volatile("ldmatrix.sync.aligned.m8n8.x4.shared.b16 {%0,%1,%2,%3}, [%4];"
        : "=r"(r[0]), "=r"(r[1]), "=r"(r[2]), "=r"(r[3]) : "r"(addr));
}
__device__ __forceinline__ void ldm_x2t(uint32_t* r, uint32_t addr) {
    asm volatile("ldmatrix.sync.aligned.m8n8.x2.trans.shared.b16 {%0,%1}, [%2];"
        : "=r"(r[0]), "=r"(r[1]) : "r"(addr));
}
__device__ __forceinline__ void mma_bf16(float* c, const uint32_t* a, const uint32_t* b) {
    asm volatile(
        "mma.sync.aligned.m16n8k16.row.col.f32.bf16.bf16.f32 "
        "{%0,%1,%2,%3}, {%4,%5,%6,%7}, {%8,%9}, {%0,%1,%2,%3};"
        : "+f"(c[0]), "+f"(c[1]), "+f"(c[2]), "+f"(c[3])
        : "r"(a[0]), "r"(a[1]), "r"(a[2]), "r"(a[3]), "r"(b[0]), "r"(b[1]));
}

// ================= tensor-core GEMM: C[M,N] = A[M,K] @ W[K,N] ==============
// bf16x3 split (hi*hi + hi*lo + lo*hi), fp32 accumulate.
// Block 128x128, K-tile 32, double-buffered smem, register prefetch.
// Smem per buffer: Ahi[128][40]b16 (10240) | Alo (10240) | Bhi[32][136]b16 (8704) | Blo (8704)
#define GM_BUF 37888
#define GM_SMEM (2 * GM_BUF)

__global__ void __launch_bounds__(256) gemm_mma(
    const float* __restrict__ A, const float* __restrict__ W, float* __restrict__ C,
    int M, int N, int K)
{
    extern __shared__ char smem[];
    const uint32_t sb = smem_u32(smem);
    const int tid = threadIdx.x;
    const int wid = tid >> 5, lane = tid & 31;
    const int m0 = blockIdx.y * 128;
    const int n0blk = blockIdx.x * 128;
    const int warp_m = wid >> 2;      // 0..1 -> 64 rows each
    const int warp_n = wid & 3;       // 0..3 -> 32 cols each

    float acc[4][4][4];
#pragma unroll
    for (int i = 0; i < 4; i++)
#pragma unroll
        for (int j = 0; j < 4; j++)
#pragma unroll
            for (int k = 0; k < 4; k++) acc[i][j][k] = 0.f;

    // load assignments
    const int ar = tid >> 1, ah = tid & 1;   // A: row, k-half (16 floats)
    const int bkr = tid >> 3, bq = tid & 7;  // B: k-row, 16-col quarter

    float aregs[16], bregs[16];

    const int KT = K >> 5;

    // prologue: load + convert tile 0
    {
        const float* ap = A + (size_t)(m0 + ar) * K + ah * 16;
#pragma unroll
        for (int j = 0; j < 4; j++) *(float4*)(aregs + j * 4) = *(const float4*)(ap + j * 4);
        const float* wp = W + (size_t)bkr * N + n0blk + bq * 16;
#pragma unroll
        for (int j = 0; j < 4; j++) {
            int col = n0blk + bq * 16 + j * 4;
            *(float4*)(bregs + j * 4) = (col < N) ? *(const float4*)(wp + j * 4)
                                                  : make_float4(0.f, 0.f, 0.f, 0.f);
        }
        char* base = smem;
        uint4 hi, lo;
        cvt8_hilo(aregs, hi, lo);
        *(uint4*)(base + ar * 80 + ah * 32) = hi;
        *(uint4*)(base + 10240 + ar * 80 + ah * 32) = lo;
        cvt8_hilo(aregs + 8, hi, lo);
        *(uint4*)(base + ar * 80 + ah * 32 + 16) = hi;
        *(uint4*)(base + 10240 + ar * 80 + ah * 32 + 16) = lo;
        cvt8_hilo(bregs, hi, lo);
        *(uint4*)(base + 20480 + bkr * 272 + bq * 32) = hi;
        *(uint4*)(base + 29184 + bkr * 272 + bq * 32) = lo;
        cvt8_hilo(bregs + 8, hi, lo);
        *(uint4*)(base + 20480 + bkr * 272 + bq * 32 + 16) = hi;
        *(uint4*)(base + 29184 + bkr * 272 + bq * 32 + 16) = lo;
    }
    __syncthreads();

    for (int kt = 0; kt < KT; kt++) {
        const int buf = kt & 1;
        const bool more = (kt + 1 < KT);
        // prefetch next tile's fp32 into registers (hides gmem latency behind MMA)
        if (more) {
            const int k0n = (kt + 1) << 5;
            const float* ap = A + (size_t)(m0 + ar) * K + k0n + ah * 16;
#pragma unroll
            for (int j = 0; j < 4; j++) *(float4*)(aregs + j * 4) = *(const float4*)(ap + j * 4);
            const float* wp = W + (size_t)(k0n + bkr) * N + n0blk + bq * 16;
#pragma unroll
            for (int j = 0; j < 4; j++) {
                int col = n0blk + bq * 16 + j * 4;
                *(float4*)(bregs + j * 4) = (col < N) ? *(const float4*)(wp + j * 4)
                                                      : make_float4(0.f, 0.f, 0.f, 0.f);
            }
        }

        // MMAs on current buffer
        const uint32_t sAhi = sb + buf * GM_BUF;
        const uint32_t sAlo = sAhi + 10240;
        const uint32_t sBhi = sAhi + 20480;
        const uint32_t sBlo = sAhi + 29184;
#pragma unroll
        for (int ks = 0; ks < 2; ks++) {
            uint32_t a_hi[4][4], a_lo[4][4], b_hi[4][2], b_lo[4][2];
#pragma unroll
            for (int mi = 0; mi < 4; mi++) {
                int row = warp_m * 64 + mi * 16 + (lane & 15);
                uint32_t addr = row * 80 + ks * 32 + (lane >> 4) * 16;
                ldm_x4(a_hi[mi], sAhi + addr);
                ldm_x4(a_lo[mi], sAlo + addr);
            }
#pragma unroll
            for (int ni = 0; ni < 4; ni++) {
                int krow = ks * 16 + (lane & 15);
                int ncol = warp_n * 32 + ni * 8;
                uint32_t addr = krow * 272 + ncol * 2;
                ldm_x2t(b_hi[ni], sBhi + addr);
                ldm_x2t(b_lo[ni], sBlo + addr);
            }
#pragma unroll
            for (int mi = 0; mi < 4; mi++)
#pragma unroll
                for (int ni = 0; ni < 4; ni++) {
                    mma_bf16(acc[mi][ni], a_hi[mi], b_hi[ni]);
                    mma_bf16(acc[mi][ni], a_hi[mi], b_lo[ni]);
                    mma_bf16(acc[mi][ni], a_lo[mi], b_hi[ni]);
                }
        }

        // convert + store prefetched tile into the other buffer
        if (more) {
            char* base = smem + (buf ^ 1) * GM_BUF;
            uint4 hi, lo;
            cvt8_hilo(aregs, hi, lo);
            *(uint4*)(base + ar * 80 + ah * 32) = hi;
            *(uint4*)(base + 10240 + ar * 80 + ah * 32) = lo;
            cvt8_hilo(aregs + 8, hi, lo);
            *(uint4*)(base + ar * 80 + ah * 32 + 16) = hi;
            *(uint4*)(base + 10240 + ar * 80 + ah * 32 + 16) = lo;
            cvt8_hilo(bregs, hi, lo);
            *(uint4*)(base + 20480 + bkr * 272 + bq * 32) = hi;
            *(uint4*)(base + 29184 + bkr * 272 + bq * 32) = lo;
            cvt8_hilo(bregs + 8, hi, lo);
            *(uint4*)(base + 20480 + bkr * 272 + bq * 32 + 16) = hi;
            *(uint4*)(base + 29184 + bkr * 272 + bq * 32 + 16) = lo;
        }
        __syncthreads();
    }

    // epilogue: fragment layout c0,c1 -> (row, col..col+1); c2,c3 -> (row+8, ..)
#pragma unroll
    for (int mi = 0; mi < 4; mi++) {
        int row = m0 + warp_m * 64 + mi * 16 + (lane >> 2);
#pragma unroll
        for (int ni = 0; ni < 4; ni++) {
            int col = n0blk + warp_n * 32 + ni * 8 + (lane & 3) * 2;
            if (col < N) {
                *(float2*)(C + (size_t)row * N + col) =
                    make_float2(acc[mi][ni][0], acc[mi][ni][1]);
                *(float2*)(C + (size_t)(row + 8) * N + col) =
                    make_float2(acc[mi][ni][2], acc[mi][ni][3]);
            }
        }
    }
}

// ---------------- dt = softplus(raw + bias) ----------------
__global__ void dt_kernel(const float* __restrict__ dt_bias) {
    int i = blockIdx.x * blockDim.x + threadIdx.x;
    if (i >= ROWS * NH) return;
    int row = i / NH, h = i % NH;
    float x = g_zx[(size_t)row * DIN + (DIN - NH) + h] + dt_bias[h];
    g_dt[i] = softplusf(x);
}

// ---------------- depthwise causal conv width-4 + silu + split -------------
__global__ void conv_kernel(const float* __restrict__ init_conv,
                            const float* __restrict__ conv_w,
                            const float* __restrict__ conv_b)
{
    int d = blockIdx.x * blockDim.x + threadIdx.x;
    if (d >= CD) return;
    int t = blockIdx.y;
    int b = blockIdx.z;
    float acc = conv_b[d];
#pragma unroll
    for (int k = 0; k < 4; k++) {
        int ti = t + k - 3;
        float v;
        if (ti >= 0) v = g_zx[(size_t)(b * L_ + ti) * DIN + NI + d];
        else         v = init_conv[((size_t)b * CD + d) * NCONV + (4 + ti)];
        acc += conv_w[d * 4 + k] * v;
    }
    float o = siluf(acc);
    int row = b * L_ + t;
    if (d < NI)           g_x [(size_t)row * NI + d] = o;
    else if (d < NI + NS) g_Bm[(size_t)row * NS + (d - NI)] = o;
    else                  g_Cm[(size_t)row * NS + (d - NI - NS)] = o;
}

// ---------------- new_conv_state output ----------------
__global__ void convstate_kernel(float* __restrict__ out) {
    int i = blockIdx.x * blockDim.x + threadIdx.x;
    if (i >= B_ * CD * NCONV) return;
    int k = i % NCONV;
    int d = (i / NCONV) % CD;
    int b = i / (NCONV * CD);
    out[i] = g_zx[(size_t)(b * L_ + (L_ - 4 + k)) * DIN + NI + d];
}

// ---------------- per-chunk Gram matrix G[l][s] = sum_n C[l,n]B[s,n] -------
__global__ void __launch_bounds__(256) gmat_kernel() {
    const int bc = blockIdx.x;
    const int b = bc / NC, c = bc % NC;
    const int row0 = b * L_ + c * CH;
    const int tid = threadIdx.x;
    __shared__ float sC[64 * 33];
    __shared__ float sB[64 * 33];
    const int l = tid >> 2;
    const int s0 = (tid & 3) * 16;
    float acc[16];
#pragma unroll
    for (int j = 0; j < 16; j++) acc[j] = 0.f;
    for (int n0 = 0; n0 < NS; n0 += 32) {
        for (int i = tid; i < 64 * 32; i += 256) {
            int r = i >> 5, nn = i & 31;
            sC[r * 33 + nn] = g_Cm[(size_t)(row0 + r) * NS + n0 + nn];
            sB[r * 33 + nn] = g_Bm[(size_t)(row0 + r) * NS + n0 + nn];
        }
        __syncthreads();
        for (int nn = 0; nn < 32; nn++) {
            float cv = sC[l * 33 + nn];
#pragma unroll
            for (int j = 0; j < 16; j++) acc[j] += cv * sB[(s0 + j) * 33 + nn];
        }
        __syncthreads();
    }
    float* Gp = g_G + (size_t)bc * (CH * CH);
#pragma unroll
    for (int j = 0; j < 16; j++) Gp[l * 64 + s0 + j] = acc[j];
}

// ---------------- per-chunk states[p][n] = sum_l B[l,n]*decay[l]*dt[l]*x[l,p]
__global__ void __launch_bounds__(256) states_kernel(const float* __restrict__ A_log) {
    const int h = blockIdx.x, c = blockIdx.y, b = blockIdx.z;
    const int tid = threadIdx.x;
    __shared__ float sdt[64], acs[64], w[64];
    __shared__ float asum_s;
    __shared__ float xs[64][64];
    __shared__ float sB[64][65];
    const int row0 = b * L_ + c * CH;
    if (tid < 64) sdt[tid] = g_dt[(size_t)(row0 + tid) * NH + h];
    __syncthreads();
    if (tid == 0) {
        float A = -expf(A_log[h]);
        float s = 0.f;
        for (int l = 0; l < 64; l++) { s += A * sdt[l]; acs[l] = s; }
        asum_s = s;
        g_asum[(b * NC + c) * NH + h] = s;
    }
    __syncthreads();
    if (tid < 64) w[tid] = expf(asum_s - acs[tid]) * sdt[tid];
    __syncthreads();
    for (int i = tid; i < 64 * 64; i += 256) {
        int l = i >> 6, p = i & 63;
        xs[l][p] = g_x[(size_t)(row0 + l) * NI + h * HD + p] * w[l];
    }
    const int pg = tid >> 5;
    const int ng = tid & 31;
    float* outp = g_st + (size_t)((b * NC + c) * NH + h) * HD * NS;
    for (int n0 = 0; n0 < NS; n0 += 64) {
        for (int i = tid; i < 64 * 64; i += 256) {
            int l = i >> 6, n = i & 63;
            sB[l][n] = g_Bm[(size_t)(row0 + l) * NS + n0 + n];
        }
        __syncthreads();
        float acc0[8], acc1[8];
#pragma unroll
        for (int i = 0; i < 8; i++) { acc0[i] = 0.f; acc1[i] = 0.f; }
        for (int l = 0; l < 64; l++) {
            float b0 = sB[l][ng * 2 + 0];
            float b1 = sB[l][ng * 2 + 1];
#pragma unroll
            for (int i = 0; i < 8; i++) {
                float xv = xs[l][pg * 8 + i];
                acc0[i] += xv * b0;
                acc1[i] += xv * b1;
            }
        }
#pragma unroll
        for (int i = 0; i < 8; i++) {
            outp[(size_t)(pg * 8 + i) * NS + n0 + ng * 2 + 0] = acc0[i];
            outp[(size_t)(pg * 8 + i) * NS + n0 + ng * 2 + 1] = acc1[i];
        }
        __syncthreads();
    }
}

// ---------------- cross-chunk state scan ----------------
__global__ void __launch_bounds__(256) scan_kernel(const float* __restrict__ init_ssm,
                                                   float* __restrict__ final_out)
{
    const int seg = blockIdx.x;
    const int h = blockIdx.y, b = blockIdx.z;
    const int tid = threadIdx.x;
    const int e = seg * 1024 + tid * 4;
    const size_t base_bh = (size_t)(b * NH + h) * HD * NS;
    float4 S = *reinterpret_cast<const float4*>(init_ssm + base_bh + e);
    for (int c = 0; c < NC; c++) {
        float dec = expf(g_asum[(b * NC + c) * NH + h]);
        float* ptr = g_st + (size_t)((b * NC + c) * NH + h) * HD * NS + e;
        float4 cs = *reinterpret_cast<float4*>(ptr);
        *reinterpret_cast<float4*>(ptr) = S;
        S.x = dec * S.x + cs.x;
        S.y = dec * S.y + cs.y;
        S.z = dec * S.z + cs.z;
        S.w = dec * S.w + cs.w;
    }
    *reinterpret_cast<float4*>(final_out + base_bh + e) = S;
}

// ---------------- Y = (G∘L)@xdt + exp(Acs)*(C @ Sprev^T) + x*D ------------
__global__ void __launch_bounds__(256) y_kernel(const float* __restrict__ A_log,
                                                const float* __restrict__ Dp)
{
    const int h = blockIdx.x, c = blockIdx.y, b = blockIdx.z;
    const int tid = threadIdx.x;
    __shared__ float sh1[64 * 65];
    __shared__ float sh2[64 * 65];
    __shared__ float acs[64], sdt[64];
    const int row0 = b * L_ + c * CH;
    if (tid < 64) sdt[tid] = g_dt[(size_t)(row0 + tid) * NH + h];
    __syncthreads();
    if (tid == 0) {
        float A = -expf(A_log[h]);
        float s = 0.f;
        for (int l = 0; l < 64; l++) { s += A * sdt[l]; acs[l] = s; }
    }
    __syncthreads();
    const int l = tid >> 2;
    const int p0 = (tid & 3) * 16;
    float acc[16];
#pragma unroll
    for (int j = 0; j < 16; j++) acc[j] = 0.f;

    const float* Sp = g_st + (size_t)((b * NC + c) * NH + h) * HD * NS;
    for (int n0 = 0; n0 < NS; n0 += 32) {
        for (int i = tid; i < 64 * 32; i += 256) {
            int r = i >> 5, nn = i & 31;
            sh1[r * 33 + nn] = g_Cm[(size_t)(row0 + r) * NS + n0 + nn];
            sh2[r * 33 + nn] = Sp[(size_t)r * NS + n0 + nn];
        }
        __syncthreads();
        for (int nn = 0; nn < 32; nn++) {
            float cv = sh1[l * 33 + nn];
#pragma unroll
            for (int j = 0; j < 16; j++) acc[j] += cv * sh2[(p0 + j) * 33 + nn];
        }
        __syncthreads();
    }
    float eAl = expf(acs[l]);
#pragma unroll
    for (int j = 0; j < 16; j++) acc[j] *= eAl;

    const float* Gp = g_G + (size_t)(b * NC + c) * (CH * CH);
    for (int i = tid; i < 64 * 64; i += 256) {
        int r = i >> 6, s = i & 63;
        sh1[r * 65 + s] = (s <= r) ? Gp[i] * expf(acs[r] - acs[s]) : 0.f;
        sh2[r * 65 + s] = g_x[(size_t)(row0 + r) * NI + h * HD + s] * sdt[r];
    }
    __syncthreads();
    for (int s = 0; s < 64; s++) {
        float gv = sh1[l * 65 + s];
#pragma unroll
        for (int j = 0; j < 16; j++) acc[j] += gv * sh2[s * 65 + p0 + j];
    }
    float Dv = Dp[h];
#pragma unroll
    for (int j = 0; j < 16; j++) {
        size_t idx = (size_t)(row0 + l) * NI + h * HD + p0 + j;
        g_yin[idx] = acc[j] + g_x[idx] * Dv;
    }
}

// ---------------- gate with silu(z), RMSNorm, * norm_w ----------------
__global__ void __launch_bounds__(256) gate_rms_kernel(const float* __restrict__ norm_w) {
    const int row = blockIdx.x;
    const int tid = threadIdx.x;
    const float* zrow = g_zx + (size_t)row * DIN;
    const float* yrow = g_yin + (size_t)row * NI;
    float v[8];
    float ss = 0.f;
#pragma unroll
    for (int i = 0; i < 8; i++) {
        int idx = tid + i * 256;
        float z = zrow[idx];
        float val = yrow[idx] * siluf(z);
        v[i] = val;
        ss += val * val;
    }
    __shared__ float red[256];
    red[tid] = ss;
    __syncthreads();
    for (int s = 128; s > 0; s >>= 1) {
        if (tid < s) red[tid] += red[tid + s];
        __syncthreads();
    }
    float scale = rsqrtf(red[0] / (float)NI + 1e-5f);
#pragma unroll
    for (int i = 0; i < 8; i++) {
        int idx = tid + i * 256;
        g_yn[(size_t)row * NI + idx] = v[i] * scale * norm_w[idx];
    }
}

// ---------------- launch ----------------
static float* symaddr(const void* sym) {
    void* p = nullptr;
    cudaGetSymbolAddress(&p, sym);
    return (float*)p;
}

extern "C" void kernel_launch(void* const* d_in, const int* in_sizes, int n_in,
                              void* d_out, int out_size)
{
    const float* u         = (const float*)d_in[0];
    const float* init_conv = (const float*)d_in[1];
    const float* init_ssm  = (const float*)d_in[2];
    const float* w_in      = (const float*)d_in[3];
    const float* conv_w    = (const float*)d_in[4];
    const float* conv_b    = (const float*)d_in[5];
    const float* dt_bias   = (const float*)d_in[6];
    const float* A_log     = (const float*)d_in[7];
    const float* Dp        = (const float*)d_in[8];
    const float* norm_w    = (const float*)d_in[9];
    const float* w_out     = (const float*)d_in[10];

    float* out       = (float*)d_out;
    float* out_y     = out;
    float* out_conv  = out + (size_t)ROWS * E_;
    float* out_final = out_conv + (size_t)B_ * CD * NCONV;

    float* pzx = symaddr(g_zx);
    float* pyn = symaddr(g_yn);

    cudaFuncSetAttribute(gemm_mma, cudaFuncAttributeMaxDynamicSharedMemorySize, GM_SMEM);

    // 1) in-projection: zxbcdt = u @ w_in   [8192,1024]x[1024,4384]
    gemm_mma<<<dim3((DIN + 127) / 128, ROWS / 128), 256, GM_SMEM>>>(u, w_in, pzx, ROWS, DIN, E_);
    // 2) dt
    dt_kernel<<<(ROWS * NH + 255) / 256, 256>>>(dt_bias);
    // 3) conv + silu + split
    conv_kernel<<<dim3((CD + 255) / 256, L_, B_), 256>>>(init_conv, conv_w, conv_b);
    // 4) new_conv_state output
    convstate_kernel<<<(B_ * CD * NCONV + 255) / 256, 256>>>(out_conv);
    // 5) per-chunk Gram matrix
    gmat_kernel<<<B_ * NC, 256>>>();
    // 6) per-chunk states
    states_kernel<<<dim3(NH, NC, B_), 256>>>(A_log);
    // 7) cross-chunk scan
    scan_kernel<<<dim3(8, NH, B_), 256>>>(init_ssm, out_final);
    // 8) Y
    y_kernel<<<dim3(NH, NC, B_), 256>>>(A_log, Dp);
    // 9) gate + rmsnorm
    gate_rms_kernel<<<ROWS, 256>>>(norm_w);
    // 10) out-projection: y = yn @ w_out  [8192,2048]x[2048,1024]
    gemm_mma<<<dim3(E_ / 128, ROWS / 128), 256, GM_SMEM>>>(pyn, w_out, out_y, ROWS, E_, NI);
}

// round 6
// speedup vs baseline: 1.7413x; 1.1879x over previous
#include <cuda_runtime.h>
#include <cuda_bf16.h>
#include <math.h>
#include <stdint.h>

// Problem constants
#define B_    2
#define L_    4096
#define E_    1024
#define NI    2048      // N_INNER
#define NS    128       // N_STATE
#define NH    32        // N_HEAD
#define HD    64        // HEADDIM
#define NCONV 4
#define CH    64        // CHUNK
#define NC    64        // chunks per sequence (L/CHUNK)
#define CD    2304      // CONV_DIM = NI + 2*NS
#define DIN   4384      // 2*NI + 2*NS + NH
#define NPAD  4480      // DIN padded to multiple of 128
#define ROWS  (B_*L_)   // 8192

// ---------------- scratch (device globals; no allocation allowed) ----------
__device__ float g_zx[(size_t)ROWS * DIN];
__device__ float g_x [(size_t)ROWS * NI];
__device__ float g_Bm[(size_t)ROWS * NS];
__device__ float g_Cm[(size_t)ROWS * NS];
__device__ float g_dt[(size_t)ROWS * NH];
__device__ float g_G [(size_t)B_ * NC * CH * CH];
__device__ float g_st[(size_t)B_ * NC * NH * HD * NS];
__device__ float g_asum[B_ * NC * NH];
__device__ float g_yin[(size_t)ROWS * NI];

// bf16 hi/lo operand copies for tensor-core GEMMs
__device__ __nv_bfloat16 g_u_hi[(size_t)ROWS * E_];
__device__ __nv_bfloat16 g_u_lo[(size_t)ROWS * E_];
__device__ __nv_bfloat16 g_win_hi[(size_t)E_ * NPAD];
__device__ __nv_bfloat16 g_win_lo[(size_t)E_ * NPAD];
__device__ __nv_bfloat16 g_wout_hi[(size_t)NI * E_];
__device__ __nv_bfloat16 g_wout_lo[(size_t)NI * E_];
__device__ __nv_bfloat16 g_ynb_hi[(size_t)ROWS * NI];
__device__ __nv_bfloat16 g_ynb_lo[(size_t)ROWS * NI];

// ---------------- small helpers ----------------
__device__ __forceinline__ float siluf(float x) { return x / (1.f + expf(-x)); }
__device__ __forceinline__ float softplusf(float x) {
    return (x > 20.f) ? x : log1pf(expf(x));
}
__device__ __forceinline__ uint32_t smem_u32(const void* p) {
    uint32_t a;
    asm("{ .reg .u64 t; cvta.to.shared.u64 t, %1; cvt.u32.u64 %0, t; }" : "=r"(a) : "l"(p));
    return a;
}

// ---------------- warp-MMA primitives (sm_80+, valid on base sm_100) -------
__device__ __forceinline__ void ldm_x4(uint32_t* r, uint32_t addr) {
    asm volatile("ldmatrix.sync.aligned.m8n8.x4.shared.b16 {%0,%1,%2,%3}, [%4];"
        : "=r"(r[0]), "=r"(r[1]), "=r"(r[2]), "=r"(r[3]) : "r"(addr));
}
__device__ __forceinline__ void ldm_x2t(uint32_t* r, uint32_t addr) {
    asm volatile("ldmatrix.sync.aligned.m8n8.x2.trans.shared.b16 {%0,%1}, [%2];"
        : "=r"(r[0]), "=r"(r[1]) : "r"(addr));
}
__device__ __forceinline__ void mma_bf16(float* c, const uint32_t* a, const uint32_t* b) {
    asm volatile(
        "mma.sync.aligned.m16n8k16.row.col.f32.bf16.bf16.f32 "
        "{%0,%1,%2,%3}, {%4,%5,%6,%7}, {%8,%9}, {%0,%1,%2,%3};"
        : "+f"(c[0]), "+f"(c[1]), "+f"(c[2]), "+f"(c[3])
        : "r"(a[0]), "r"(a[1]), "r"(a[2]), "r"(a[3]), "r"(b[0]), "r"(b[1]));
}
__device__ __forceinline__ void cp16(uint32_t dst, const void* src) {
    asm volatile("cp.async.cg.shared.global [%0], [%1], 16;" :: "r"(dst), "l"(src));
}
#define CP_COMMIT() asm volatile("cp.async.commit_group;" ::: "memory")
#define CP_WAIT(n)  asm volatile("cp.async.wait_group %0;" :: "n"(n) : "memory")

// ---------------- fp32 -> bf16 hi/lo conversion kernels ----------------
__global__ void cvt_hilo_kernel(const float* __restrict__ s,
                                __nv_bfloat16* __restrict__ hi,
                                __nv_bfloat16* __restrict__ lo, int n)
{
    int i = (blockIdx.x * blockDim.x + threadIdx.x) * 4;
    if (i >= n) return;
    float4 v = *(const float4*)(s + i);
    float f[4] = {v.x, v.y, v.z, v.w};
    ushort hh[4], ll[4];
#pragma unroll
    for (int j = 0; j < 4; j++) {
        __nv_bfloat16 h = __float2bfloat16_rn(f[j]);
        __nv_bfloat16 l = __float2bfloat16_rn(f[j] - __bfloat162float(h));
        hh[j] = __bfloat16_as_ushort(h);
        ll[j] = __bfloat16_as_ushort(l);
    }
    *(ushort4*)((ushort*)hi + i) = make_ushort4(hh[0], hh[1], hh[2], hh[3]);
    *(ushort4*)((ushort*)lo + i) = make_ushort4(ll[0], ll[1], ll[2], ll[3]);
}

// w_in [E_][DIN] -> padded [E_][NPAD] hi/lo (zero-fill cols >= DIN)
__global__ void cvt_win_kernel(const float* __restrict__ w) {
    int i4 = (blockIdx.x * blockDim.x + threadIdx.x) * 4;
    if (i4 >= E_ * NPAD) return;
    int row = i4 / NPAD, col = i4 % NPAD;
    float f[4];
    if (col + 3 < DIN) {
        float4 v = *(const float4*)(w + (size_t)row * DIN + col);
        f[0] = v.x; f[1] = v.y; f[2] = v.z; f[3] = v.w;
    } else {
#pragma unroll
        for (int j = 0; j < 4; j++) {
            int cc = col + j;
            f[j] = (cc < DIN) ? w[(size_t)row * DIN + cc] : 0.f;
        }
    }
    ushort hh[4], ll[4];
#pragma unroll
    for (int j = 0; j < 4; j++) {
        __nv_bfloat16 h = __float2bfloat16_rn(f[j]);
        __nv_bfloat16 l = __float2bfloat16_rn(f[j] - __bfloat162float(h));
        hh[j] = __bfloat16_as_ushort(h);
        ll[j] = __bfloat16_as_ushort(l);
    }
    *(ushort4*)((ushort*)g_win_hi + i4) = make_ushort4(hh[0], hh[1], hh[2], hh[3]);
    *(ushort4*)((ushort*)g_win_lo + i4) = make_ushort4(ll[0], ll[1], ll[2], ll[3]);
}

// ================= tensor-core GEMM: C[M,N] = A[M,K] @ B[K,N] ==============
// bf16x3 split (hi*hi + hi*lo + lo*hi), fp32 accumulate.
// Inputs pre-converted to bf16 hi/lo. cp.async 4-stage pipeline, K-tile 32.
// Stage layout: Ahi[128][40]b16 (10240) | Alo (10240) | Bhi[32][136]b16 (8704) | Blo (8704)
#define ST_A_LO 10240
#define ST_B_HI 20480
#define ST_B_LO 29184
#define ST_BYTES 37888
#define STG 4
#define GM_SMEM (STG * ST_BYTES)

__global__ void __launch_bounds__(256) gemm_bf16(
    const __nv_bfloat16* __restrict__ Ah, const __nv_bfloat16* __restrict__ Al,
    const __nv_bfloat16* __restrict__ Bh, const __nv_bfloat16* __restrict__ Bl,
    float* __restrict__ C, int M, int N, int K, int ldB)
{
    extern __shared__ char smem[];
    const uint32_t sb = smem_u32(smem);
    const int tid = threadIdx.x;
    const int wid = tid >> 5, lane = tid & 31;
    const int m0 = blockIdx.y * 128;
    const int n0 = blockIdx.x * 128;
    const int warp_m = wid >> 2;      // 0..1 -> 64 rows
    const int warp_n = wid & 3;       // 0..3 -> 32 cols

    float acc[4][4][4];
#pragma unroll
    for (int i = 0; i < 4; i++)
#pragma unroll
        for (int j = 0; j < 4; j++)
#pragma unroll
            for (int k = 0; k < 4; k++) acc[i][j][k] = 0.f;

    const int KTn = K >> 5;

    // A chunk task: c in [0,512): row=c>>2, 16B chunk=c&3
    const int arow0 = tid >> 2, ach0 = tid & 3;          // j=0
    const int arow1 = (tid + 256) >> 2, ach1 = tid & 3;  // j=1
    // B chunk task: c in [0,512): krow=c>>4, chunk=c&15
    const int bkr0 = tid >> 4, bch0 = tid & 15;
    const int bkr1 = (tid + 256) >> 4, bch1 = tid & 15;

#define LOAD_STAGE(KT_) do { \
    const int k0_ = (KT_) << 5; \
    const uint32_t st_ = sb + ((KT_) % STG) * ST_BYTES; \
    { size_t go = (size_t)(m0 + arow0) * K + k0_ + ach0 * 8; \
      uint32_t so = st_ + arow0 * 80 + ach0 * 16; \
      cp16(so, Ah + go); cp16(so + ST_A_LO, Al + go); } \
    { size_t go = (size_t)(m0 + arow1) * K + k0_ + ach1 * 8; \
      uint32_t so = st_ + arow1 * 80 + ach1 * 16; \
      cp16(so, Ah + go); cp16(so + ST_A_LO, Al + go); } \
    { size_t go = (size_t)(k0_ + bkr0) * ldB + n0 + bch0 * 8; \
      uint32_t so = st_ + ST_B_HI + bkr0 * 272 + bch0 * 16; \
      cp16(so, Bh + go); cp16(so + 8704, Bl + go); } \
    { size_t go = (size_t)(k0_ + bkr1) * ldB + n0 + bch1 * 8; \
      uint32_t so = st_ + ST_B_HI + bkr1 * 272 + bch1 * 16; \
      cp16(so, Bh + go); cp16(so + 8704, Bl + go); } \
} while (0)

    // prologue: fill STG-1 stages
#pragma unroll
    for (int s = 0; s < STG - 1; s++) {
        if (s < KTn) LOAD_STAGE(s);
        CP_COMMIT();
    }

    for (int kt = 0; kt < KTn; kt++) {
        CP_WAIT(STG - 2);
        __syncthreads();
        const uint32_t sAhi = sb + (kt % STG) * ST_BYTES;
        const uint32_t sAlo = sAhi + ST_A_LO;
        const uint32_t sBhi = sAhi + ST_B_HI;
        const uint32_t sBlo = sAhi + ST_B_LO;
#pragma unroll
        for (int ks = 0; ks < 2; ks++) {
            uint32_t a_hi[4][4], a_lo[4][4], b_hi[4][2], b_lo[4][2];
#pragma unroll
            for (int mi = 0; mi < 4; mi++) {
                int row = warp_m * 64 + mi * 16 + (lane & 15);
                uint32_t addr = row * 80 + ks * 32 + (lane >> 4) * 16;
                ldm_x4(a_hi[mi], sAhi + addr);
                ldm_x4(a_lo[mi], sAlo + addr);
            }
#pragma unroll
            for (int ni = 0; ni < 4; ni++) {
                int krow = ks * 16 + (lane & 15);
                int ncol = warp_n * 32 + ni * 8;
                uint32_t addr = krow * 272 + ncol * 2;
                ldm_x2t(b_hi[ni], sBhi + addr);
                ldm_x2t(b_lo[ni], sBlo + addr);
            }
#pragma unroll
            for (int mi = 0; mi < 4; mi++)
#pragma unroll
                for (int ni = 0; ni < 4; ni++) {
                    mma_bf16(acc[mi][ni], a_hi[mi], b_hi[ni]);
                    mma_bf16(acc[mi][ni], a_hi[mi], b_lo[ni]);
                    mma_bf16(acc[mi][ni], a_lo[mi], b_hi[ni]);
                }
        }
        if (kt + STG - 1 < KTn) LOAD_STAGE(kt + STG - 1);
        CP_COMMIT();
    }
#undef LOAD_STAGE

    // epilogue
#pragma unroll
    for (int mi = 0; mi < 4; mi++) {
        int row = m0 + warp_m * 64 + mi * 16 + (lane >> 2);
#pragma unroll
        for (int ni = 0; ni < 4; ni++) {
            int col = n0 + warp_n * 32 + ni * 8 + (lane & 3) * 2;
            if (col < N) {
                *(float2*)(C + (size_t)row * N + col) =
                    make_float2(acc[mi][ni][0], acc[mi][ni][1]);
                *(float2*)(C + (size_t)(row + 8) * N + col) =
                    make_float2(acc[mi][ni][2], acc[mi][ni][3]);
            }
        }
    }
}

// ---------------- dt = softplus(raw + bias) ----------------
__global__ void dt_kernel(const float* __restrict__ dt_bias) {
    int i = blockIdx.x * blockDim.x + threadIdx.x;
    if (i >= ROWS * NH) return;
    int row = i / NH, h = i % NH;
    float x = g_zx[(size_t)row * DIN + (DIN - NH) + h] + dt_bias[h];
    g_dt[i] = softplusf(x);
}

// ---------------- depthwise causal conv width-4 + silu + split -------------
__global__ void conv_kernel(const float* __restrict__ init_conv,
                            const float* __restrict__ conv_w,
                            const float* __restrict__ conv_b)
{
    int d = blockIdx.x * blockDim.x + threadIdx.x;
    if (d >= CD) return;
    int t = blockIdx.y;
    int b = blockIdx.z;
    float acc = conv_b[d];
#pragma unroll
    for (int k = 0; k < 4; k++) {
        int ti = t + k - 3;
        float v;
        if (ti >= 0) v = g_zx[(size_t)(b * L_ + ti) * DIN + NI + d];
        else         v = init_conv[((size_t)b * CD + d) * NCONV + (4 + ti)];
        acc += conv_w[d * 4 + k] * v;
    }
    float o = siluf(acc);
    int row = b * L_ + t;
    if (d < NI)           g_x [(size_t)row * NI + d] = o;
    else if (d < NI + NS) g_Bm[(size_t)row * NS + (d - NI)] = o;
    else                  g_Cm[(size_t)row * NS + (d - NI - NS)] = o;
}

// ---------------- new_conv_state output ----------------
__global__ void convstate_kernel(float* __restrict__ out) {
    int i = blockIdx.x * blockDim.x + threadIdx.x;
    if (i >= B_ * CD * NCONV) return;
    int k = i % NCONV;
    int d = (i / NCONV) % CD;
    int b = i / (NCONV * CD);
    out[i] = g_zx[(size_t)(b * L_ + (L_ - 4 + k)) * DIN + NI + d];
}

// ---------------- per-chunk Gram matrix G[l][s] = sum_n C[l,n]B[s,n] -------
__global__ void __launch_bounds__(256) gmat_kernel() {
    const int bc = blockIdx.x;
    const int b = bc / NC, c = bc % NC;
    const int row0 = b * L_ + c * CH;
    const int tid = threadIdx.x;
    __shared__ float sC[64 * 33];
    __shared__ float sB[64 * 33];
    const int l = tid >> 2;
    const int s0 = (tid & 3) * 16;
    float acc[16];
#pragma unroll
    for (int j = 0; j < 16; j++) acc[j] = 0.f;
    for (int n0 = 0; n0 < NS; n0 += 32) {
        for (int i = tid; i < 64 * 32; i += 256) {
            int r = i >> 5, nn = i & 31;
            sC[r * 33 + nn] = g_Cm[(size_t)(row0 + r) * NS + n0 + nn];
            sB[r * 33 + nn] = g_Bm[(size_t)(row0 + r) * NS + n0 + nn];
        }
        __syncthreads();
        for (int nn = 0; nn < 32; nn++) {
            float cv = sC[l * 33 + nn];
#pragma unroll
            for (int j = 0; j < 16; j++) acc[j] += cv * sB[(s0 + j) * 33 + nn];
        }
        __syncthreads();
    }
    float* Gp = g_G + (size_t)bc * (CH * CH);
#pragma unroll
    for (int j = 0; j < 16; j++) Gp[l * 64 + s0 + j] = acc[j];
}

// ---------------- per-chunk states[p][n] = sum_l B[l,n]*decay[l]*dt[l]*x[l,p]
__global__ void __launch_bounds__(256) states_kernel(const float* __restrict__ A_log) {
    const int h = blockIdx.x, c = blockIdx.y, b = blockIdx.z;
    const int tid = threadIdx.x;
    __shared__ float sdt[64], acs[64], w[64];
    __shared__ float asum_s;
    __shared__ float xs[64][64];
    __shared__ float sB[64][65];
    const int row0 = b * L_ + c * CH;
    if (tid < 64) sdt[tid] = g_dt[(size_t)(row0 + tid) * NH + h];
    __syncthreads();
    if (tid == 0) {
        float A = -expf(A_log[h]);
        float s = 0.f;
        for (int l = 0; l < 64; l++) { s += A * sdt[l]; acs[l] = s; }
        asum_s = s;
        g_asum[(b * NC + c) * NH + h] = s;
    }
    __syncthreads();
    if (tid < 64) w[tid] = expf(asum_s - acs[tid]) * sdt[tid];
    __syncthreads();
    for (int i = tid; i < 64 * 64; i += 256) {
        int l = i >> 6, p = i & 63;
        xs[l][p] = g_x[(size_t)(row0 + l) * NI + h * HD + p] * w[l];
    }
    const int pg = tid >> 5;
    const int ng = tid & 31;
    float* outp = g_st + (size_t)((b * NC + c) * NH + h) * HD * NS;
    for (int n0 = 0; n0 < NS; n0 += 64) {
        for (int i = tid; i < 64 * 64; i += 256) {
            int l = i >> 6, n = i & 63;
            sB[l][n] = g_Bm[(size_t)(row0 + l) * NS + n0 + n];
        }
        __syncthreads();
        float acc0[8], acc1[8];
#pragma unroll
        for (int i = 0; i < 8; i++) { acc0[i] = 0.f; acc1[i] = 0.f; }
        for (int l = 0; l < 64; l++) {
            float b0 = sB[l][ng * 2 + 0];
            float b1 = sB[l][ng * 2 + 1];
#pragma unroll
            for (int i = 0; i < 8; i++) {
                float xv = xs[l][pg * 8 + i];
                acc0[i] += xv * b0;
                acc1[i] += xv * b1;
            }
        }
#pragma unroll
        for (int i = 0; i < 8; i++) {
            outp[(size_t)(pg * 8 + i) * NS + n0 + ng * 2 + 0] = acc0[i];
            outp[(size_t)(pg * 8 + i) * NS + n0 + ng * 2 + 1] = acc1[i];
        }
        __syncthreads();
    }
}

// ---------------- cross-chunk state scan ----------------
__global__ void __launch_bounds__(256) scan_kernel(const float* __restrict__ init_ssm,
                                                   float* __restrict__ final_out)
{
    const int seg = blockIdx.x;
    const int h = blockIdx.y, b = blockIdx.z;
    const int tid = threadIdx.x;
    const int e = seg * 1024 + tid * 4;
    const size_t base_bh = (size_t)(b * NH + h) * HD * NS;
    float4 S = *reinterpret_cast<const float4*>(init_ssm + base_bh + e);
    for (int c = 0; c < NC; c++) {
        float dec = expf(g_asum[(b * NC + c) * NH + h]);
        float* ptr = g_st + (size_t)((b * NC + c) * NH + h) * HD * NS + e;
        float4 cs = *reinterpret_cast<float4*>(ptr);
        *reinterpret_cast<float4*>(ptr) = S;
        S.x = dec * S.x + cs.x;
        S.y = dec * S.y + cs.y;
        S.z = dec * S.z + cs.z;
        S.w = dec * S.w + cs.w;
    }
    *reinterpret_cast<float4*>(final_out + base_bh + e) = S;
}

// ---------------- Y = (G∘L)@xdt + exp(Acs)*(C @ Sprev^T) + x*D ------------
__global__ void __launch_bounds__(256) y_kernel(const float* __restrict__ A_log,
                                                const float* __restrict__ Dp)
{
    const int h = blockIdx.x, c = blockIdx.y, b = blockIdx.z;
    const int tid = threadIdx.x;
    __shared__ float sh1[64 * 65];
    __shared__ float sh2[64 * 65];
    __shared__ float acs[64], sdt[64];
    const int row0 = b * L_ + c * CH;
    if (tid < 64) sdt[tid] = g_dt[(size_t)(row0 + tid) * NH + h];
    __syncthreads();
    if (tid == 0) {
        float A = -expf(A_log[h]);
        float s = 0.f;
        for (int l = 0; l < 64; l++) { s += A * sdt[l]; acs[l] = s; }
    }
    __syncthreads();
    const int l = tid >> 2;
    const int p0 = (tid & 3) * 16;
    float acc[16];
#pragma unroll
    for (int j = 0; j < 16; j++) acc[j] = 0.f;

    const float* Sp = g_st + (size_t)((b * NC + c) * NH + h) * HD * NS;
    for (int n0 = 0; n0 < NS; n0 += 32) {
        for (int i = tid; i < 64 * 32; i += 256) {
            int r = i >> 5, nn = i & 31;
            sh1[r * 33 + nn] = g_Cm[(size_t)(row0 + r) * NS + n0 + nn];
            sh2[r * 33 + nn] = Sp[(size_t)r * NS + n0 + nn];
        }
        __syncthreads();
        for (int nn = 0; nn < 32; nn++) {
            float cv = sh1[l * 33 + nn];
#pragma unroll
            for (int j = 0; j < 16; j++) acc[j] += cv * sh2[(p0 + j) * 33 + nn];
        }
        __syncthreads();
    }
    float eAl = expf(acs[l]);
#pragma unroll
    for (int j = 0; j < 16; j++) acc[j] *= eAl;

    const float* Gp = g_G + (size_t)(b * NC + c) * (CH * CH);
    for (int i = tid; i < 64 * 64; i += 256) {
        int r = i >> 6, s = i & 63;
        sh1[r * 65 + s] = (s <= r) ? Gp[i] * expf(acs[r] - acs[s]) : 0.f;
        sh2[r * 65 + s] = g_x[(size_t)(row0 + r) * NI + h * HD + s] * sdt[r];
    }
    __syncthreads();
    for (int s = 0; s < 64; s++) {
        float gv = sh1[l * 65 + s];
#pragma unroll
        for (int j = 0; j < 16; j++) acc[j] += gv * sh2[s * 65 + p0 + j];
    }
    float Dv = Dp[h];
#pragma unroll
    for (int j = 0; j < 16; j++) {
        size_t idx = (size_t)(row0 + l) * NI + h * HD + p0 + j;
        g_yin[idx] = acc[j] + g_x[idx] * Dv;
    }
}

// ------ gate with silu(z), RMSNorm, * norm_w; emit bf16 hi/lo directly ------
__global__ void __launch_bounds__(256) gate_rms_kernel(const float* __restrict__ norm_w) {
    const int row = blockIdx.x;
    const int tid = threadIdx.x;
    const float* zrow = g_zx + (size_t)row * DIN;
    const float* yrow = g_yin + (size_t)row * NI;
    float v[8];
    float ss = 0.f;
#pragma unroll
    for (int i = 0; i < 8; i++) {
        int idx = tid + i * 256;
        float z = zrow[idx];
        float val = yrow[idx] * siluf(z);
        v[i] = val;
        ss += val * val;
    }
    __shared__ float red[256];
    red[tid] = ss;
    __syncthreads();
    for (int s = 128; s > 0; s >>= 1) {
        if (tid < s) red[tid] += red[tid + s];
        __syncthreads();
    }
    float scale = rsqrtf(red[0] / (float)NI + 1e-5f);
#pragma unroll
    for (int i = 0; i < 8; i++) {
        int idx = tid + i * 256;
        float o = v[i] * scale * norm_w[idx];
        __nv_bfloat16 h = __float2bfloat16_rn(o);
        __nv_bfloat16 lo = __float2bfloat16_rn(o - __bfloat162float(h));
        g_ynb_hi[(size_t)row * NI + idx] = h;
        g_ynb_lo[(size_t)row * NI + idx] = lo;
    }
}

// ---------------- launch ----------------
template <typename T>
static T* symaddr(const void* sym) {
    void* p = nullptr;
    cudaGetSymbolAddress(&p, sym);
    return (T*)p;
}

extern "C" void kernel_launch(void* const* d_in, const int* in_sizes, int n_in,
                              void* d_out, int out_size)
{
    const float* u         = (const float*)d_in[0];
    const float* init_conv = (const float*)d_in[1];
    const float* init_ssm  = (const float*)d_in[2];
    const float* w_in      = (const float*)d_in[3];
    const float* conv_w    = (const float*)d_in[4];
    const float* conv_b    = (const float*)d_in[5];
    const float* dt_bias   = (const float*)d_in[6];
    const float* A_log     = (const float*)d_in[7];
    const float* Dp        = (const float*)d_in[8];
    const float* norm_w    = (const float*)d_in[9];
    const float* w_out     = (const float*)d_in[10];

    float* out       = (float*)d_out;
    float* out_y     = out;
    float* out_conv  = out + (size_t)ROWS * E_;
    float* out_final = out_conv + (size_t)B_ * CD * NCONV;

    float* pzx = symaddr<float>(g_zx);
    __nv_bfloat16* p_u_hi  = symaddr<__nv_bfloat16>(g_u_hi);
    __nv_bfloat16* p_u_lo  = symaddr<__nv_bfloat16>(g_u_lo);
    __nv_bfloat16* p_win_hi  = symaddr<__nv_bfloat16>(g_win_hi);
    __nv_bfloat16* p_win_lo  = symaddr<__nv_bfloat16>(g_win_lo);
    __nv_bfloat16* p_wout_hi = symaddr<__nv_bfloat16>(g_wout_hi);
    __nv_bfloat16* p_wout_lo = symaddr<__nv_bfloat16>(g_wout_lo);
    __nv_bfloat16* p_yn_hi = symaddr<__nv_bfloat16>(g_ynb_hi);
    __nv_bfloat16* p_yn_lo = symaddr<__nv_bfloat16>(g_ynb_lo);

    cudaFuncSetAttribute(gemm_bf16, cudaFuncAttributeMaxDynamicSharedMemorySize, GM_SMEM);

    // 0) operand conversions to bf16 hi/lo
    cvt_hilo_kernel<<<(ROWS * E_ / 4 + 511) / 512, 512>>>(u, p_u_hi, p_u_lo, ROWS * E_);
    cvt_win_kernel<<<(E_ * NPAD / 4 + 511) / 512, 512>>>(w_in);
    cvt_hilo_kernel<<<(NI * E_ / 4 + 511) / 512, 512>>>(w_out, p_wout_hi, p_wout_lo, NI * E_);

    // 1) in-projection: zxbcdt = u @ w_in   [8192,1024]x[1024,4384]
    gemm_bf16<<<dim3(NPAD / 128, ROWS / 128), 256, GM_SMEM>>>(
        p_u_hi, p_u_lo, p_win_hi, p_win_lo, pzx, ROWS, DIN, E_, NPAD);
    // 2) dt
    dt_kernel<<<(ROWS * NH + 255) / 256, 256>>>(dt_bias);
    // 3) conv + silu + split
    conv_kernel<<<dim3((CD + 255) / 256, L_, B_), 256>>>(init_conv, conv_w, conv_b);
    // 4) new_conv_state output
    convstate_kernel<<<(B_ * CD * NCONV + 255) / 256, 256>>>(out_conv);
    // 5) per-chunk Gram matrix
    gmat_kernel<<<B_ * NC, 256>>>();
    // 6) per-chunk states
    states_kernel<<<dim3(NH, NC, B_), 256>>>(A_log);
    // 7) cross-chunk scan
    scan_kernel<<<dim3(8, NH, B_), 256>>>(init_ssm, out_final);
    // 8) Y
    y_kernel<<<dim3(NH, NC, B_), 256>>>(A_log, Dp);
    // 9) gate + rmsnorm (emits bf16 hi/lo)
    gate_rms_kernel<<<ROWS, 256>>>(norm_w);
    // 10) out-projection: y = yn @ w_out  [8192,2048]x[2048,1024]
    gemm_bf16<<<dim3(E_ / 128, ROWS / 128), 256, GM_SMEM>>>(
        p_yn_hi, p_yn_lo, p_wout_hi, p_wout_lo, out_y, ROWS, E_, NI, E_);
}

// round 7
// speedup vs baseline: 1.8457x; 1.0600x over previous
#include <cuda_runtime.h>
#include <cuda_bf16.h>
#include <math.h>
#include <stdint.h>

// Problem constants
#define B_    2
#define L_    4096
#define E_    1024
#define NI    2048      // N_INNER
#define NS    128       // N_STATE
#define NH    32        // N_HEAD
#define HD    64        // HEADDIM
#define NCONV 4
#define CH    64        // CHUNK
#define NC    64        // chunks per sequence (L/CHUNK)
#define CD    2304      // CONV_DIM = NI + 2*NS
#define DIN   4384      // 2*NI + 2*NS + NH
#define NPAD  4480      // DIN padded to multiple of 128
#define ROWS  (B_*L_)   // 8192

// ---------------- scratch (device globals; no allocation allowed) ----------
__device__ float g_zx[(size_t)ROWS * DIN];
__device__ float g_x [(size_t)ROWS * NI];
__device__ float g_Bm[(size_t)ROWS * NS];
__device__ float g_Cm[(size_t)ROWS * NS];
__device__ float g_dt[(size_t)ROWS * NH];
__device__ float g_G [(size_t)B_ * NC * CH * CH];
__device__ float g_st[(size_t)B_ * NC * NH * HD * NS];
__device__ float g_asum[B_ * NC * NH];
__device__ float g_yin[(size_t)ROWS * NI];

// bf16 hi/lo operand copies for tensor-core GEMMs
__device__ __nv_bfloat16 g_u_hi[(size_t)ROWS * E_];
__device__ __nv_bfloat16 g_u_lo[(size_t)ROWS * E_];
__device__ __nv_bfloat16 g_win_hi[(size_t)E_ * NPAD];
__device__ __nv_bfloat16 g_win_lo[(size_t)E_ * NPAD];
__device__ __nv_bfloat16 g_wout_hi[(size_t)NI * E_];
__device__ __nv_bfloat16 g_wout_lo[(size_t)NI * E_];
__device__ __nv_bfloat16 g_ynb_hi[(size_t)ROWS * NI];
__device__ __nv_bfloat16 g_ynb_lo[(size_t)ROWS * NI];

// ---------------- small helpers ----------------
__device__ __forceinline__ float siluf(float x) { return x / (1.f + expf(-x)); }
__device__ __forceinline__ float softplusf(float x) {
    return (x > 20.f) ? x : log1pf(expf(x));
}
__device__ __forceinline__ uint32_t smem_u32(const void* p) {
    uint32_t a;
    asm("{ .reg .u64 t; cvta.to.shared.u64 t, %1; cvt.u32.u64 %0, t; }" : "=r"(a) : "l"(p));
    return a;
}

// ---------------- warp-MMA primitives (sm_80+, valid on base sm_100) -------
__device__ __forceinline__ void ldm_x4(uint32_t* r, uint32_t addr) {
    asm volatile("ldmatrix.sync.aligned.m8n8.x4.shared.b16 {%0,%1,%2,%3}, [%4];"
        : "=r"(r[0]), "=r"(r[1]), "=r"(r[2]), "=r"(r[3]) : "r"(addr));
}
__device__ __forceinline__ void ldm_x2t(uint32_t* r, uint32_t addr) {
    asm volatile("ldmatrix.sync.aligned.m8n8.x2.trans.shared.b16 {%0,%1}, [%2];"
        : "=r"(r[0]), "=r"(r[1]) : "r"(addr));
}
__device__ __forceinline__ void mma_bf16(float* c, const uint32_t* a, const uint32_t* b) {
    asm volatile(
        "mma.sync.aligned.m16n8k16.row.col.f32.bf16.bf16.f32 "
        "{%0,%1,%2,%3}, {%4,%5,%6,%7}, {%8,%9}, {%0,%1,%2,%3};"
        : "+f"(c[0]), "+f"(c[1]), "+f"(c[2]), "+f"(c[3])
        : "r"(a[0]), "r"(a[1]), "r"(a[2]), "r"(a[3]), "r"(b[0]), "r"(b[1]));
}
__device__ __forceinline__ void cp16(uint32_t dst, const void* src) {
    asm volatile("cp.async.cg.shared.global [%0], [%1], 16;" :: "r"(dst), "l"(src));
}
#define CP_COMMIT() asm volatile("cp.async.commit_group;" ::: "memory")
#define CP_WAIT(n)  asm volatile("cp.async.wait_group %0;" :: "n"(n) : "memory")

// ---------------- fp32 -> bf16 hi/lo conversion kernels ----------------
__global__ void cvt_hilo_kernel(const float* __restrict__ s,
                                __nv_bfloat16* __restrict__ hi,
                                __nv_bfloat16* __restrict__ lo, int n)
{
    int i = (blockIdx.x * blockDim.x + threadIdx.x) * 4;
    if (i >= n) return;
    float4 v = *(const float4*)(s + i);
    float f[4] = {v.x, v.y, v.z, v.w};
    ushort hh[4], ll[4];
#pragma unroll
    for (int j = 0; j < 4; j++) {
        __nv_bfloat16 h = __float2bfloat16_rn(f[j]);
        __nv_bfloat16 l = __float2bfloat16_rn(f[j] - __bfloat162float(h));
        hh[j] = __bfloat16_as_ushort(h);
        ll[j] = __bfloat16_as_ushort(l);
    }
    *(ushort4*)((ushort*)hi + i) = make_ushort4(hh[0], hh[1], hh[2], hh[3]);
    *(ushort4*)((ushort*)lo + i) = make_ushort4(ll[0], ll[1], ll[2], ll[3]);
}

// w_in [E_][DIN] -> padded [E_][NPAD] hi/lo (zero-fill cols >= DIN)
__global__ void cvt_win_kernel(const float* __restrict__ w) {
    int i4 = (blockIdx.x * blockDim.x + threadIdx.x) * 4;
    if (i4 >= E_ * NPAD) return;
    int row = i4 / NPAD, col = i4 % NPAD;
    float f[4];
    if (col + 3 < DIN) {
        float4 v = *(const float4*)(w + (size_t)row * DIN + col);
        f[0] = v.x; f[1] = v.y; f[2] = v.z; f[3] = v.w;
    } else {
#pragma unroll
        for (int j = 0; j < 4; j++) {
            int cc = col + j;
            f[j] = (cc < DIN) ? w[(size_t)row * DIN + cc] : 0.f;
        }
    }
    ushort hh[4], ll[4];
#pragma unroll
    for (int j = 0; j < 4; j++) {
        __nv_bfloat16 h = __float2bfloat16_rn(f[j]);
        __nv_bfloat16 l = __float2bfloat16_rn(f[j] - __bfloat162float(h));
        hh[j] = __bfloat16_as_ushort(h);
        ll[j] = __bfloat16_as_ushort(l);
    }
    *(ushort4*)((ushort*)g_win_hi + i4) = make_ushort4(hh[0], hh[1], hh[2], hh[3]);
    *(ushort4*)((ushort*)g_win_lo + i4) = make_ushort4(ll[0], ll[1], ll[2], ll[3]);
}

// ================= tensor-core GEMM: C[M,N] = A[M,K] @ B[K,N] ==============
// bf16x3 split (hi*hi + hi*lo + lo*hi), fp32 accumulate.
// Block tile 256x128, 512 threads (16 warps: 4m x 4n, 64x32 per warp).
// K-tile 32, cp.async 3-stage pipeline.
// Stage: Ahi[256][40]b16 (20480) | Alo (20480) | Bhi[32][136]b16 (8704) | Blo (8704)
#define ST_A_LO 20480
#define ST_B_HI 40960
#define ST_B_LO 49664
#define ST_BYTES 58368
#define STG 3
#define GM_SMEM (STG * ST_BYTES)

__global__ void __launch_bounds__(512, 1) gemm_bf16(
    const __nv_bfloat16* __restrict__ Ah, const __nv_bfloat16* __restrict__ Al,
    const __nv_bfloat16* __restrict__ Bh, const __nv_bfloat16* __restrict__ Bl,
    float* __restrict__ C, int M, int N, int K, int ldB)
{
    extern __shared__ char smem[];
    const uint32_t sb = smem_u32(smem);
    const int tid = threadIdx.x;
    const int wid = tid >> 5, lane = tid & 31;
    const int m0 = blockIdx.y * 256;
    const int n0 = blockIdx.x * 128;
    const int warp_m = wid >> 2;      // 0..3 -> 64 rows each
    const int warp_n = wid & 3;       // 0..3 -> 32 cols each

    float acc[4][4][4];
#pragma unroll
    for (int i = 0; i < 4; i++)
#pragma unroll
        for (int j = 0; j < 4; j++)
#pragma unroll
            for (int k = 0; k < 4; k++) acc[i][j][k] = 0.f;

    const int KTn = K >> 5;

    // A chunk c in [0,1024): row=c>>2 (0..255), ch=c&3 ; thread does c=tid, tid+512
    const int arow0 = tid >> 2, ach0 = tid & 3;
    const int arow1 = (tid + 512) >> 2, ach1 = tid & 3;
    // B chunk c in [0,512): krow=c>>4 (0..31), ch=c&15 ; thread does c=tid (tid<512)
    const int bkr = tid >> 4, bch = tid & 15;

#define LOAD_STAGE(KT_) do { \
    const int k0_ = (KT_) << 5; \
    const uint32_t st_ = sb + ((KT_) % STG) * ST_BYTES; \
    { size_t go = (size_t)(m0 + arow0) * K + k0_ + ach0 * 8; \
      uint32_t so = st_ + arow0 * 80 + ach0 * 16; \
      cp16(so, Ah + go); cp16(so + ST_A_LO, Al + go); } \
    { size_t go = (size_t)(m0 + arow1) * K + k0_ + ach1 * 8; \
      uint32_t so = st_ + arow1 * 80 + ach1 * 16; \
      cp16(so, Ah + go); cp16(so + ST_A_LO, Al + go); } \
    { size_t go = (size_t)(k0_ + bkr) * ldB + n0 + bch * 8; \
      uint32_t so = st_ + ST_B_HI + bkr * 272 + bch * 16; \
      cp16(so, Bh + go); cp16(so + 8704, Bl + go); } \
} while (0)

    // prologue: fill STG-1 stages
#pragma unroll
    for (int s = 0; s < STG - 1; s++) {
        if (s < KTn) LOAD_STAGE(s);
        CP_COMMIT();
    }

    for (int kt = 0; kt < KTn; kt++) {
        CP_WAIT(STG - 2);
        __syncthreads();
        const uint32_t sAhi = sb + (kt % STG) * ST_BYTES;
        const uint32_t sAlo = sAhi + ST_A_LO;
        const uint32_t sBhi = sAhi + ST_B_HI;
        const uint32_t sBlo = sAhi + ST_B_LO;
#pragma unroll
        for (int ks = 0; ks < 2; ks++) {
            uint32_t a_hi[4][4], a_lo[4][4], b_hi[4][2], b_lo[4][2];
#pragma unroll
            for (int mi = 0; mi < 4; mi++) {
                int row = warp_m * 64 + mi * 16 + (lane & 15);
                uint32_t addr = row * 80 + ks * 32 + (lane >> 4) * 16;
                ldm_x4(a_hi[mi], sAhi + addr);
                ldm_x4(a_lo[mi], sAlo + addr);
            }
#pragma unroll
            for (int ni = 0; ni < 4; ni++) {
                int krow = ks * 16 + (lane & 15);
                int ncol = warp_n * 32 + ni * 8;
                uint32_t addr = krow * 272 + ncol * 2;
                ldm_x2t(b_hi[ni], sBhi + addr);
                ldm_x2t(b_lo[ni], sBlo + addr);
            }
#pragma unroll
            for (int mi = 0; mi < 4; mi++)
#pragma unroll
                for (int ni = 0; ni < 4; ni++) {
                    mma_bf16(acc[mi][ni], a_hi[mi], b_hi[ni]);
                    mma_bf16(acc[mi][ni], a_hi[mi], b_lo[ni]);
                    mma_bf16(acc[mi][ni], a_lo[mi], b_hi[ni]);
                }
        }
        if (kt + STG - 1 < KTn) LOAD_STAGE(kt + STG - 1);
        CP_COMMIT();
    }
#undef LOAD_STAGE

    // epilogue
#pragma unroll
    for (int mi = 0; mi < 4; mi++) {
        int row = m0 + warp_m * 64 + mi * 16 + (lane >> 2);
#pragma unroll
        for (int ni = 0; ni < 4; ni++) {
            int col = n0 + warp_n * 32 + ni * 8 + (lane & 3) * 2;
            if (col < N) {
                *(float2*)(C + (size_t)row * N + col) =
                    make_float2(acc[mi][ni][0], acc[mi][ni][1]);
                *(float2*)(C + (size_t)(row + 8) * N + col) =
                    make_float2(acc[mi][ni][2], acc[mi][ni][3]);
            }
        }
    }
}

// ---------------- dt = softplus(raw + bias) ----------------
__global__ void dt_kernel(const float* __restrict__ dt_bias) {
    int i = blockIdx.x * blockDim.x + threadIdx.x;
    if (i >= ROWS * NH) return;
    int row = i / NH, h = i % NH;
    float x = g_zx[(size_t)row * DIN + (DIN - NH) + h] + dt_bias[h];
    g_dt[i] = softplusf(x);
}

// ------ depthwise causal conv width-4 + silu + split; 8 timesteps/thread ---
__global__ void conv_kernel(const float* __restrict__ init_conv,
                            const float* __restrict__ conv_w,
                            const float* __restrict__ conv_b)
{
    int d = blockIdx.x * blockDim.x + threadIdx.x;
    if (d >= CD) return;
    const int t0 = blockIdx.y * 8;
    const int b = blockIdx.z;
    float w0 = conv_w[d * 4 + 0], w1 = conv_w[d * 4 + 1];
    float w2 = conv_w[d * 4 + 2], w3 = conv_w[d * 4 + 3];
    float bias = conv_b[d];
    float win[11];
#pragma unroll
    for (int i = 0; i < 11; i++) {
        int ti = t0 - 3 + i;
        if (ti >= 0) win[i] = g_zx[(size_t)(b * L_ + ti) * DIN + NI + d];
        else         win[i] = init_conv[((size_t)b * CD + d) * NCONV + (4 + ti)];
    }
#pragma unroll
    for (int j = 0; j < 8; j++) {
        float acc = bias + w0 * win[j] + w1 * win[j + 1] + w2 * win[j + 2] + w3 * win[j + 3];
        float o = siluf(acc);
        int row = b * L_ + t0 + j;
        if (d < NI)           g_x [(size_t)row * NI + d] = o;
        else if (d < NI + NS) g_Bm[(size_t)row * NS + (d - NI)] = o;
        else                  g_Cm[(size_t)row * NS + (d - NI - NS)] = o;
    }
}

// ---------------- new_conv_state output ----------------
__global__ void convstate_kernel(float* __restrict__ out) {
    int i = blockIdx.x * blockDim.x + threadIdx.x;
    if (i >= B_ * CD * NCONV) return;
    int k = i % NCONV;
    int d = (i / NCONV) % CD;
    int b = i / (NCONV * CD);
    out[i] = g_zx[(size_t)(b * L_ + (L_ - 4 + k)) * DIN + NI + d];
}

// ---------------- per-chunk Gram matrix G[l][s] = sum_n C[l,n]B[s,n] -------
__global__ void __launch_bounds__(256) gmat_kernel() {
    const int bc = blockIdx.x;
    const int b = bc / NC, c = bc % NC;
    const int row0 = b * L_ + c * CH;
    const int tid = threadIdx.x;
    __shared__ float sC[64 * 33];
    __shared__ float sB[64 * 33];
    const int l = tid >> 2;
    const int s0 = (tid & 3) * 16;
    float acc[16];
#pragma unroll
    for (int j = 0; j < 16; j++) acc[j] = 0.f;
    for (int n0 = 0; n0 < NS; n0 += 32) {
        for (int i = tid; i < 64 * 32; i += 256) {
            int r = i >> 5, nn = i & 31;
            sC[r * 33 + nn] = g_Cm[(size_t)(row0 + r) * NS + n0 + nn];
            sB[r * 33 + nn] = g_Bm[(size_t)(row0 + r) * NS + n0 + nn];
        }
        __syncthreads();
        for (int nn = 0; nn < 32; nn++) {
            float cv = sC[l * 33 + nn];
#pragma unroll
            for (int j = 0; j < 16; j++) acc[j] += cv * sB[(s0 + j) * 33 + nn];
        }
        __syncthreads();
    }
    float* Gp = g_G + (size_t)bc * (CH * CH);
#pragma unroll
    for (int j = 0; j < 16; j++) Gp[l * 64 + s0 + j] = acc[j];
}

// ---------------- per-chunk states[p][n] = sum_l B[l,n]*decay[l]*dt[l]*x[l,p]
__global__ void __launch_bounds__(256) states_kernel(const float* __restrict__ A_log) {
    const int h = blockIdx.x, c = blockIdx.y, b = blockIdx.z;
    const int tid = threadIdx.x;
    __shared__ float sdt[64], acs[64], w[64];
    __shared__ float asum_s;
    __shared__ float xs[64][64];
    __shared__ float sB[64][65];
    const int row0 = b * L_ + c * CH;
    if (tid < 64) sdt[tid] = g_dt[(size_t)(row0 + tid) * NH + h];
    __syncthreads();
    if (tid == 0) {
        float A = -expf(A_log[h]);
        float s = 0.f;
        for (int l = 0; l < 64; l++) { s += A * sdt[l]; acs[l] = s; }
        asum_s = s;
        g_asum[(b * NC + c) * NH + h] = s;
    }
    __syncthreads();
    if (tid < 64) w[tid] = expf(asum_s - acs[tid]) * sdt[tid];
    __syncthreads();
    for (int i = tid; i < 64 * 64; i += 256) {
        int l = i >> 6, p = i & 63;
        xs[l][p] = g_x[(size_t)(row0 + l) * NI + h * HD + p] * w[l];
    }
    const int pg = tid >> 5;
    const int ng = tid & 31;
    float* outp = g_st + (size_t)((b * NC + c) * NH + h) * HD * NS;
    for (int n0 = 0; n0 < NS; n0 += 64) {
        for (int i = tid; i < 64 * 64; i += 256) {
            int l = i >> 6, n = i & 63;
            sB[l][n] = g_Bm[(size_t)(row0 + l) * NS + n0 + n];
        }
        __syncthreads();
        float acc0[8], acc1[8];
#pragma unroll
        for (int i = 0; i < 8; i++) { acc0[i] = 0.f; acc1[i] = 0.f; }
        for (int l = 0; l < 64; l++) {
            float b0 = sB[l][ng * 2 + 0];
            float b1 = sB[l][ng * 2 + 1];
#pragma unroll
            for (int i = 0; i < 8; i++) {
                float xv = xs[l][pg * 8 + i];
                acc0[i] += xv * b0;
                acc1[i] += xv * b1;
            }
        }
#pragma unroll
        for (int i = 0; i < 8; i++) {
            outp[(size_t)(pg * 8 + i) * NS + n0 + ng * 2 + 0] = acc0[i];
            outp[(size_t)(pg * 8 + i) * NS + n0 + ng * 2 + 1] = acc1[i];
        }
        __syncthreads();
    }
}

// ---------------- cross-chunk state scan ----------------
__global__ void __launch_bounds__(256) scan_kernel(const float* __restrict__ init_ssm,
                                                   float* __restrict__ final_out)
{
    const int seg = blockIdx.x;
    const int h = blockIdx.y, b = blockIdx.z;
    const int tid = threadIdx.x;
    const int e = seg * 1024 + tid * 4;
    const size_t base_bh = (size_t)(b * NH + h) * HD * NS;
    float4 S = *reinterpret_cast<const float4*>(init_ssm + base_bh + e);
    for (int c = 0; c < NC; c++) {
        float dec = expf(g_asum[(b * NC + c) * NH + h]);
        float* ptr = g_st + (size_t)((b * NC + c) * NH + h) * HD * NS + e;
        float4 cs = *reinterpret_cast<float4*>(ptr);
        *reinterpret_cast<float4*>(ptr) = S;
        S.x = dec * S.x + cs.x;
        S.y = dec * S.y + cs.y;
        S.z = dec * S.z + cs.z;
        S.w = dec * S.w + cs.w;
    }
    *reinterpret_cast<float4*>(final_out + base_bh + e) = S;
}

// ---------------- Y = (G∘L)@xdt + exp(Acs)*(C @ Sprev^T) + x*D ------------
__global__ void __launch_bounds__(256) y_kernel(const float* __restrict__ A_log,
                                                const float* __restrict__ Dp)
{
    const int h = blockIdx.x, c = blockIdx.y, b = blockIdx.z;
    const int tid = threadIdx.x;
    __shared__ float sh1[64 * 65];
    __shared__ float sh2[64 * 65];
    __shared__ float acs[64], sdt[64];
    const int row0 = b * L_ + c * CH;
    if (tid < 64) sdt[tid] = g_dt[(size_t)(row0 + tid) * NH + h];
    __syncthreads();
    if (tid == 0) {
        float A = -expf(A_log[h]);
        float s = 0.f;
        for (int l = 0; l < 64; l++) { s += A * sdt[l]; acs[l] = s; }
    }
    __syncthreads();
    const int l = tid >> 2;
    const int p0 = (tid & 3) * 16;
    float acc[16];
#pragma unroll
    for (int j = 0; j < 16; j++) acc[j] = 0.f;

    const float* Sp = g_st + (size_t)((b * NC + c) * NH + h) * HD * NS;
    for (int n0 = 0; n0 < NS; n0 += 32) {
        for (int i = tid; i < 64 * 32; i += 256) {
            int r = i >> 5, nn = i & 31;
            sh1[r * 33 + nn] = g_Cm[(size_t)(row0 + r) * NS + n0 + nn];
            sh2[r * 33 + nn] = Sp[(size_t)r * NS + n0 + nn];
        }
        __syncthreads();
        for (int nn = 0; nn < 32; nn++) {
            float cv = sh1[l * 33 + nn];
#pragma unroll
            for (int j = 0; j < 16; j++) acc[j] += cv * sh2[(p0 + j) * 33 + nn];
        }
        __syncthreads();
    }
    float eAl = expf(acs[l]);
#pragma unroll
    for (int j = 0; j < 16; j++) acc[j] *= eAl;

    const float* Gp = g_G + (size_t)(b * NC + c) * (CH * CH);
    for (int i = tid; i < 64 * 64; i += 256) {
        int r = i >> 6, s = i & 63;
        sh1[r * 65 + s] = (s <= r) ? Gp[i] * expf(acs[r] - acs[s]) : 0.f;
        sh2[r * 65 + s] = g_x[(size_t)(row0 + r) * NI + h * HD + s] * sdt[r];
    }
    __syncthreads();
    for (int s = 0; s < 64; s++) {
        float gv = sh1[l * 65 + s];
#pragma unroll
        for (int j = 0; j < 16; j++) acc[j] += gv * sh2[s * 65 + p0 + j];
    }
    float Dv = Dp[h];
#pragma unroll
    for (int j = 0; j < 16; j++) {
        size_t idx = (size_t)(row0 + l) * NI + h * HD + p0 + j;
        g_yin[idx] = acc[j] + g_x[idx] * Dv;
    }
}

// ------ gate with silu(z), RMSNorm, * norm_w; emit bf16 hi/lo directly ------
__global__ void __launch_bounds__(256) gate_rms_kernel(const float* __restrict__ norm_w) {
    const int row = blockIdx.x;
    const int tid = threadIdx.x;
    const float* zrow = g_zx + (size_t)row * DIN;
    const float* yrow = g_yin + (size_t)row * NI;
    float v[8];
    float ss = 0.f;
#pragma unroll
    for (int i = 0; i < 8; i++) {
        int idx = tid + i * 256;
        float z = zrow[idx];
        float val = yrow[idx] * siluf(z);
        v[i] = val;
        ss += val * val;
    }
    __shared__ float red[256];
    red[tid] = ss;
    __syncthreads();
    for (int s = 128; s > 0; s >>= 1) {
        if (tid < s) red[tid] += red[tid + s];
        __syncthreads();
    }
    float scale = rsqrtf(red[0] / (float)NI + 1e-5f);
#pragma unroll
    for (int i = 0; i < 8; i++) {
        int idx = tid + i * 256;
        float o = v[i] * scale * norm_w[idx];
        __nv_bfloat16 h = __float2bfloat16_rn(o);
        __nv_bfloat16 lo = __float2bfloat16_rn(o - __bfloat162float(h));
        g_ynb_hi[(size_t)row * NI + idx] = h;
        g_ynb_lo[(size_t)row * NI + idx] = lo;
    }
}

// ---------------- launch ----------------
template <typename T>
static T* symaddr(const void* sym) {
    void* p = nullptr;
    cudaGetSymbolAddress(&p, sym);
    return (T*)p;
}

extern "C" void kernel_launch(void* const* d_in, const int* in_sizes, int n_in,
                              void* d_out, int out_size)
{
    const float* u         = (const float*)d_in[0];
    const float* init_conv = (const float*)d_in[1];
    const float* init_ssm  = (const float*)d_in[2];
    const float* w_in      = (const float*)d_in[3];
    const float* conv_w    = (const float*)d_in[4];
    const float* conv_b    = (const float*)d_in[5];
    const float* dt_bias   = (const float*)d_in[6];
    const float* A_log     = (const float*)d_in[7];
    const float* Dp        = (const float*)d_in[8];
    const float* norm_w    = (const float*)d_in[9];
    const float* w_out     = (const float*)d_in[10];

    float* out       = (float*)d_out;
    float* out_y     = out;
    float* out_conv  = out + (size_t)ROWS * E_;
    float* out_final = out_conv + (size_t)B_ * CD * NCONV;

    float* pzx = symaddr<float>(g_zx);
    __nv_bfloat16* p_u_hi  = symaddr<__nv_bfloat16>(g_u_hi);
    __nv_bfloat16* p_u_lo  = symaddr<__nv_bfloat16>(g_u_lo);
    __nv_bfloat16* p_win_hi  = symaddr<__nv_bfloat16>(g_win_hi);
    __nv_bfloat16* p_win_lo  = symaddr<__nv_bfloat16>(g_win_lo);
    __nv_bfloat16* p_wout_hi = symaddr<__nv_bfloat16>(g_wout_hi);
    __nv_bfloat16* p_wout_lo = symaddr<__nv_bfloat16>(g_wout_lo);
    __nv_bfloat16* p_yn_hi = symaddr<__nv_bfloat16>(g_ynb_hi);
    __nv_bfloat16* p_yn_lo = symaddr<__nv_bfloat16>(g_ynb_lo);

    cudaFuncSetAttribute(gemm_bf16, cudaFuncAttributeMaxDynamicSharedMemorySize, GM_SMEM);

    // 0) operand conversions to bf16 hi/lo
    cvt_hilo_kernel<<<(ROWS * E_ / 4 + 511) / 512, 512>>>(u, p_u_hi, p_u_lo, ROWS * E_);
    cvt_win_kernel<<<(E_ * NPAD / 4 + 511) / 512, 512>>>(w_in);
    cvt_hilo_kernel<<<(NI * E_ / 4 + 511) / 512, 512>>>(w_out, p_wout_hi, p_wout_lo, NI * E_);

    // 1) in-projection: zxbcdt = u @ w_in   [8192,1024]x[1024,4384]
    gemm_bf16<<<dim3(NPAD / 128, ROWS / 256), 512, GM_SMEM>>>(
        p_u_hi, p_u_lo, p_win_hi, p_win_lo, pzx, ROWS, DIN, E_, NPAD);
    // 2) dt
    dt_kernel<<<(ROWS * NH + 255) / 256, 256>>>(dt_bias);
    // 3) conv + silu + split (8 timesteps per thread)
    conv_kernel<<<dim3((CD + 255) / 256, L_ / 8, B_), 256>>>(init_conv, conv_w, conv_b);
    // 4) new_conv_state output
    convstate_kernel<<<(B_ * CD * NCONV + 255) / 256, 256>>>(out_conv);
    // 5) per-chunk Gram matrix
    gmat_kernel<<<B_ * NC, 256>>>();
    // 6) per-chunk states
    states_kernel<<<dim3(NH, NC, B_), 256>>>(A_log);
    // 7) cross-chunk scan
    scan_kernel<<<dim3(8, NH, B_), 256>>>(init_ssm, out_final);
    // 8) Y
    y_kernel<<<dim3(NH, NC, B_), 256>>>(A_log, Dp);
    // 9) gate + rmsnorm (emits bf16 hi/lo)
    gate_rms_kernel<<<ROWS, 256>>>(norm_w);
    // 10) out-projection: y = yn @ w_out  [8192,2048]x[2048,1024]
    gemm_bf16<<<dim3(E_ / 128, ROWS / 256), 512, GM_SMEM>>>(
        p_yn_hi, p_yn_lo, p_wout_hi, p_wout_lo, out_y, ROWS, E_, NI, E_);
}

// round 8
// speedup vs baseline: 1.9640x; 1.0641x over previous
#include <cuda_runtime.h>
#include <cuda_bf16.h>
#include <math.h>
#include <stdint.h>

// Problem constants
#define B_    2
#define L_    4096
#define E_    1024
#define NI    2048      // N_INNER
#define NS    128       // N_STATE
#define NH    32        // N_HEAD
#define HD    64        // HEADDIM
#define NCONV 4
#define CH    64        // CHUNK
#define NC    64        // chunks per sequence (L/CHUNK)
#define CD    2304      // CONV_DIM = NI + 2*NS
#define DIN   4384      // 2*NI + 2*NS + NH
#define NPAD  4480      // DIN padded to multiple of 128
#define ROWS  (B_*L_)   // 8192

// ---------------- scratch (device globals; no allocation allowed) ----------
__device__ float g_zx[(size_t)ROWS * DIN];
__device__ float g_x [(size_t)ROWS * NI];
__device__ float g_Bm[(size_t)ROWS * NS];
__device__ float g_Cm[(size_t)ROWS * NS];
__device__ float g_dt[(size_t)ROWS * NH];
__device__ float g_G [(size_t)B_ * NC * CH * CH];
__device__ float g_st[(size_t)B_ * NC * NH * HD * NS];
__device__ float g_asum[B_ * NC * NH];
__device__ float g_yin[(size_t)ROWS * NI];

// bf16 hi/lo operand copies for tensor-core GEMMs
__device__ __nv_bfloat16 g_u_hi[(size_t)ROWS * E_];
__device__ __nv_bfloat16 g_u_lo[(size_t)ROWS * E_];
__device__ __nv_bfloat16 g_win_hi[(size_t)E_ * NPAD];
__device__ __nv_bfloat16 g_win_lo[(size_t)E_ * NPAD];
__device__ __nv_bfloat16 g_wout_hi[(size_t)NI * E_];
__device__ __nv_bfloat16 g_wout_lo[(size_t)NI * E_];
__device__ __nv_bfloat16 g_ynb_hi[(size_t)ROWS * NI];
__device__ __nv_bfloat16 g_ynb_lo[(size_t)ROWS * NI];

// ---------------- small helpers ----------------
__device__ __forceinline__ float siluf(float x) { return x / (1.f + expf(-x)); }
__device__ __forceinline__ float softplusf(float x) {
    return (x > 20.f) ? x : log1pf(expf(x));
}
__device__ __forceinline__ uint32_t smem_u32(const void* p) {
    uint32_t a;
    asm("{ .reg .u64 t; cvta.to.shared.u64 t, %1; cvt.u32.u64 %0, t; }" : "=r"(a) : "l"(p));
    return a;
}

// ---------------- warp-MMA primitives (sm_80+, valid on base sm_100) -------
__device__ __forceinline__ void ldm_x4(uint32_t* r, uint32_t addr) {
    asm volatile("ldmatrix.sync.aligned.m8n8.x4.shared.b16 {%0,%1,%2,%3}, [%4];"
        : "=r"(r[0]), "=r"(r[1]), "=r"(r[2]), "=r"(r[3]) : "r"(addr));
}
__device__ __forceinline__ void ldm_x2t(uint32_t* r, uint32_t addr) {
    asm volatile("ldmatrix.sync.aligned.m8n8.x2.trans.shared.b16 {%0,%1}, [%2];"
        : "=r"(r[0]), "=r"(r[1]) : "r"(addr));
}
__device__ __forceinline__ void mma_bf16(float* c, const uint32_t* a, const uint32_t* b) {
    asm volatile(
        "mma.sync.aligned.m16n8k16.row.col.f32.bf16.bf16.f32 "
        "{%0,%1,%2,%3}, {%4,%5,%6,%7}, {%8,%9}, {%0,%1,%2,%3};"
        : "+f"(c[0]), "+f"(c[1]), "+f"(c[2]), "+f"(c[3])
        : "r"(a[0]), "r"(a[1]), "r"(a[2]), "r"(a[3]), "r"(b[0]), "r"(b[1]));
}
__device__ __forceinline__ void cp16(uint32_t dst, const void* src) {
    asm volatile("cp.async.cg.shared.global [%0], [%1], 16;" :: "r"(dst), "l"(src));
}
#define CP_COMMIT() asm volatile("cp.async.commit_group;" ::: "memory")
#define CP_WAIT(n)  asm volatile("cp.async.wait_group %0;" :: "n"(n) : "memory")

// ---------------- fp32 -> bf16 hi/lo conversion kernels ----------------
__global__ void cvt_hilo_kernel(const float* __restrict__ s,
                                __nv_bfloat16* __restrict__ hi,
                                __nv_bfloat16* __restrict__ lo, int n)
{
    int i = (blockIdx.x * blockDim.x + threadIdx.x) * 4;
    if (i >= n) return;
    float4 v = *(const float4*)(s + i);
    float f[4] = {v.x, v.y, v.z, v.w};
    ushort hh[4], ll[4];
#pragma unroll
    for (int j = 0; j < 4; j++) {
        __nv_bfloat16 h = __float2bfloat16_rn(f[j]);
        __nv_bfloat16 l = __float2bfloat16_rn(f[j] - __bfloat162float(h));
        hh[j] = __bfloat16_as_ushort(h);
        ll[j] = __bfloat16_as_ushort(l);
    }
    *(ushort4*)((ushort*)hi + i) = make_ushort4(hh[0], hh[1], hh[2], hh[3]);
    *(ushort4*)((ushort*)lo + i) = make_ushort4(ll[0], ll[1], ll[2], ll[3]);
}

// w_in [E_][DIN] -> padded [E_][NPAD] hi/lo (zero-fill cols >= DIN)
__global__ void cvt_win_kernel(const float* __restrict__ w) {
    int i4 = (blockIdx.x * blockDim.x + threadIdx.x) * 4;
    if (i4 >= E_ * NPAD) return;
    int row = i4 / NPAD, col = i4 % NPAD;
    float f[4];
    if (col + 3 < DIN) {
        float4 v = *(const float4*)(w + (size_t)row * DIN + col);
        f[0] = v.x; f[1] = v.y; f[2] = v.z; f[3] = v.w;
    } else {
#pragma unroll
        for (int j = 0; j < 4; j++) {
            int cc = col + j;
            f[j] = (cc < DIN) ? w[(size_t)row * DIN + cc] : 0.f;
        }
    }
    ushort hh[4], ll[4];
#pragma unroll
    for (int j = 0; j < 4; j++) {
        __nv_bfloat16 h = __float2bfloat16_rn(f[j]);
        __nv_bfloat16 l = __float2bfloat16_rn(f[j] - __bfloat162float(h));
        hh[j] = __bfloat16_as_ushort(h);
        ll[j] = __bfloat16_as_ushort(l);
    }
    *(ushort4*)((ushort*)g_win_hi + i4) = make_ushort4(hh[0], hh[1], hh[2], hh[3]);
    *(ushort4*)((ushort*)g_win_lo + i4) = make_ushort4(ll[0], ll[1], ll[2], ll[3]);
}

// ================= tensor-core GEMM: C[M,N] = A[M,K] @ B[K,N] ==============
// bf16x3 split (hi*hi + hi*lo + lo*hi), fp32 accumulate.
// Block tile 256x128, 512 threads (16 warps: 4m x 4n, 64x32 per warp).
// K-tile 32, cp.async 3-stage pipeline.
#define ST_A_LO 20480
#define ST_B_HI 40960
#define ST_B_LO 49664
#define ST_BYTES 58368
#define STG 3
#define GM_SMEM (STG * ST_BYTES)

__global__ void __launch_bounds__(512, 1) gemm_bf16(
    const __nv_bfloat16* __restrict__ Ah, const __nv_bfloat16* __restrict__ Al,
    const __nv_bfloat16* __restrict__ Bh, const __nv_bfloat16* __restrict__ Bl,
    float* __restrict__ C, int M, int N, int K, int ldB)
{
    extern __shared__ char smem[];
    const uint32_t sb = smem_u32(smem);
    const int tid = threadIdx.x;
    const int wid = tid >> 5, lane = tid & 31;
    const int m0 = blockIdx.y * 256;
    const int n0 = blockIdx.x * 128;
    const int warp_m = wid >> 2;
    const int warp_n = wid & 3;

    float acc[4][4][4];
#pragma unroll
    for (int i = 0; i < 4; i++)
#pragma unroll
        for (int j = 0; j < 4; j++)
#pragma unroll
            for (int k = 0; k < 4; k++) acc[i][j][k] = 0.f;

    const int KTn = K >> 5;

    const int arow0 = tid >> 2, ach0 = tid & 3;
    const int arow1 = (tid + 512) >> 2, ach1 = tid & 3;
    const int bkr = tid >> 4, bch = tid & 15;

#define LOAD_STAGE(KT_) do { \
    const int k0_ = (KT_) << 5; \
    const uint32_t st_ = sb + ((KT_) % STG) * ST_BYTES; \
    { size_t go = (size_t)(m0 + arow0) * K + k0_ + ach0 * 8; \
      uint32_t so = st_ + arow0 * 80 + ach0 * 16; \
      cp16(so, Ah + go); cp16(so + ST_A_LO, Al + go); } \
    { size_t go = (size_t)(m0 + arow1) * K + k0_ + ach1 * 8; \
      uint32_t so = st_ + arow1 * 80 + ach1 * 16; \
      cp16(so, Ah + go); cp16(so + ST_A_LO, Al + go); } \
    { size_t go = (size_t)(k0_ + bkr) * ldB + n0 + bch * 8; \
      uint32_t so = st_ + ST_B_HI + bkr * 272 + bch * 16; \
      cp16(so, Bh + go); cp16(so + 8704, Bl + go); } \
} while (0)

#pragma unroll
    for (int s = 0; s < STG - 1; s++) {
        if (s < KTn) LOAD_STAGE(s);
        CP_COMMIT();
    }

    for (int kt = 0; kt < KTn; kt++) {
        CP_WAIT(STG - 2);
        __syncthreads();
        const uint32_t sAhi = sb + (kt % STG) * ST_BYTES;
        const uint32_t sAlo = sAhi + ST_A_LO;
        const uint32_t sBhi = sAhi + ST_B_HI;
        const uint32_t sBlo = sAhi + ST_B_LO;
#pragma unroll
        for (int ks = 0; ks < 2; ks++) {
            uint32_t a_hi[4][4], a_lo[4][4], b_hi[4][2], b_lo[4][2];
#pragma unroll
            for (int mi = 0; mi < 4; mi++) {
                int row = warp_m * 64 + mi * 16 + (lane & 15);
                uint32_t addr = row * 80 + ks * 32 + (lane >> 4) * 16;
                ldm_x4(a_hi[mi], sAhi + addr);
                ldm_x4(a_lo[mi], sAlo + addr);
            }
#pragma unroll
            for (int ni = 0; ni < 4; ni++) {
                int krow = ks * 16 + (lane & 15);
                int ncol = warp_n * 32 + ni * 8;
                uint32_t addr = krow * 272 + ncol * 2;
                ldm_x2t(b_hi[ni], sBhi + addr);
                ldm_x2t(b_lo[ni], sBlo + addr);
            }
#pragma unroll
            for (int mi = 0; mi < 4; mi++)
#pragma unroll
                for (int ni = 0; ni < 4; ni++) {
                    mma_bf16(acc[mi][ni], a_hi[mi], b_hi[ni]);
                    mma_bf16(acc[mi][ni], a_hi[mi], b_lo[ni]);
                    mma_bf16(acc[mi][ni], a_lo[mi], b_hi[ni]);
                }
        }
        if (kt + STG - 1 < KTn) LOAD_STAGE(kt + STG - 1);
        CP_COMMIT();
    }
#undef LOAD_STAGE

#pragma unroll
    for (int mi = 0; mi < 4; mi++) {
        int row = m0 + warp_m * 64 + mi * 16 + (lane >> 2);
#pragma unroll
        for (int ni = 0; ni < 4; ni++) {
            int col = n0 + warp_n * 32 + ni * 8 + (lane & 3) * 2;
            if (col < N) {
                *(float2*)(C + (size_t)row * N + col) =
                    make_float2(acc[mi][ni][0], acc[mi][ni][1]);
                *(float2*)(C + (size_t)(row + 8) * N + col) =
                    make_float2(acc[mi][ni][2], acc[mi][ni][3]);
            }
        }
    }
}

// ---------------- dt = softplus(raw + bias) ----------------
__global__ void dt_kernel(const float* __restrict__ dt_bias) {
    int i = blockIdx.x * blockDim.x + threadIdx.x;
    if (i >= ROWS * NH) return;
    int row = i / NH, h = i % NH;
    float x = g_zx[(size_t)row * DIN + (DIN - NH) + h] + dt_bias[h];
    g_dt[i] = softplusf(x);
}

// ------ depthwise causal conv width-4 + silu + split; 8 timesteps/thread ---
__global__ void conv_kernel(const float* __restrict__ init_conv,
                            const float* __restrict__ conv_w,
                            const float* __restrict__ conv_b)
{
    int d = blockIdx.x * blockDim.x + threadIdx.x;
    if (d >= CD) return;
    const int t0 = blockIdx.y * 8;
    const int b = blockIdx.z;
    float w0 = conv_w[d * 4 + 0], w1 = conv_w[d * 4 + 1];
    float w2 = conv_w[d * 4 + 2], w3 = conv_w[d * 4 + 3];
    float bias = conv_b[d];
    float win[11];
#pragma unroll
    for (int i = 0; i < 11; i++) {
        int ti = t0 - 3 + i;
        if (ti >= 0) win[i] = g_zx[(size_t)(b * L_ + ti) * DIN + NI + d];
        else         win[i] = init_conv[((size_t)b * CD + d) * NCONV + (4 + ti)];
    }
#pragma unroll
    for (int j = 0; j < 8; j++) {
        float acc = bias + w0 * win[j] + w1 * win[j + 1] + w2 * win[j + 2] + w3 * win[j + 3];
        float o = siluf(acc);
        int row = b * L_ + t0 + j;
        if (d < NI)           g_x [(size_t)row * NI + d] = o;
        else if (d < NI + NS) g_Bm[(size_t)row * NS + (d - NI)] = o;
        else                  g_Cm[(size_t)row * NS + (d - NI - NS)] = o;
    }
}

// ---------------- new_conv_state output ----------------
__global__ void convstate_kernel(float* __restrict__ out) {
    int i = blockIdx.x * blockDim.x + threadIdx.x;
    if (i >= B_ * CD * NCONV) return;
    int k = i % NCONV;
    int d = (i / NCONV) % CD;
    int b = i / (NCONV * CD);
    out[i] = g_zx[(size_t)(b * L_ + (L_ - 4 + k)) * DIN + NI + d];
}

// ---------------- per-chunk Gram matrix G[l][s] = sum_n C[l,n]B[s,n] -------
__global__ void __launch_bounds__(256) gmat_kernel() {
    const int bc = blockIdx.x;
    const int b = bc / NC, c = bc % NC;
    const int row0 = b * L_ + c * CH;
    const int tid = threadIdx.x;
    __shared__ float sC[64 * 33];
    __shared__ float sB[64 * 33];
    const int l = tid >> 2;
    const int s0 = (tid & 3) * 16;
    float acc[16];
#pragma unroll
    for (int j = 0; j < 16; j++) acc[j] = 0.f;
    for (int n0 = 0; n0 < NS; n0 += 32) {
        for (int i = tid; i < 64 * 32; i += 256) {
            int r = i >> 5, nn = i & 31;
            sC[r * 33 + nn] = g_Cm[(size_t)(row0 + r) * NS + n0 + nn];
            sB[r * 33 + nn] = g_Bm[(size_t)(row0 + r) * NS + n0 + nn];
        }
        __syncthreads();
        for (int nn = 0; nn < 32; nn++) {
            float cv = sC[l * 33 + nn];
#pragma unroll
            for (int j = 0; j < 16; j++) acc[j] += cv * sB[(s0 + j) * 33 + nn];
        }
        __syncthreads();
    }
    float* Gp = g_G + (size_t)bc * (CH * CH);
#pragma unroll
    for (int j = 0; j < 16; j++) Gp[l * 64 + s0 + j] = acc[j];
}

// ------- per-chunk states[p][n] = sum_l B[l,n]*decay[l]*dt[l]*x[l,p] -------
// xs: [64 l][68 pad] of x*w ; sB: [64 l][132 pad] of B (full 128 n)
#define STATES_SMEM ((64*68 + 64*132) * 4)
__global__ void __launch_bounds__(256) states_kernel(const float* __restrict__ A_log) {
    extern __shared__ float sm[];
    float* xs = sm;             // [64][68]
    float* sB = sm + 64 * 68;   // [64][132]
    __shared__ float sdt[64], w[64];
    __shared__ float asum_s;
    const int h = blockIdx.x, c = blockIdx.y, b = blockIdx.z;
    const int tid = threadIdx.x;
    const int row0 = b * L_ + c * CH;
    if (tid < 64) sdt[tid] = g_dt[(size_t)(row0 + tid) * NH + h];
    __syncthreads();
    if (tid == 0) {
        float A = -expf(A_log[h]);
        float s = 0.f;
        for (int l = 0; l < 64; l++) { s += A * sdt[l]; w[l] = s; }  // w = acs (temp)
        asum_s = s;
        g_asum[(b * NC + c) * NH + h] = s;
    }
    __syncthreads();
    float wv = (tid < 64) ? expf(asum_s - w[tid]) * sdt[tid] : 0.f;
    __syncthreads();
    if (tid < 64) w[tid] = wv;
    __syncthreads();

    // load x*w as [l][p], B as [l][n]
    for (int i = tid; i < 64 * 16; i += 256) {
        int l = i >> 4, q = i & 15;
        float4 v = *(const float4*)(g_x + (size_t)(row0 + l) * NI + h * HD + q * 4);
        float wl = w[l];
        *(float4*)(xs + l * 68 + q * 4) = make_float4(v.x * wl, v.y * wl, v.z * wl, v.w * wl);
    }
    for (int i = tid; i < 64 * 32; i += 256) {
        int l = i >> 5, q = i & 31;
        *(float4*)(sB + l * 132 + q * 4) =
            *(const float4*)(g_Bm + (size_t)(row0 + l) * NS + q * 4);
    }
    __syncthreads();

    const int pg = tid >> 5;   // 8 p-groups of 8
    const int ng = tid & 31;   // 32 n-pairs (x2 halves)
    float acc[8][4];
#pragma unroll
    for (int i = 0; i < 8; i++)
#pragma unroll
        for (int j = 0; j < 4; j++) acc[i][j] = 0.f;

    for (int l = 0; l < 64; l++) {
        const float* xr = xs + l * 68 + pg * 8;
        float4 xa = *(const float4*)(xr);
        float4 xb = *(const float4*)(xr + 4);
        float2 bA = *(const float2*)(sB + l * 132 + 2 * ng);
        float2 bB = *(const float2*)(sB + l * 132 + 64 + 2 * ng);
        float xv[8] = {xa.x, xa.y, xa.z, xa.w, xb.x, xb.y, xb.z, xb.w};
#pragma unroll
        for (int i = 0; i < 8; i++) {
            acc[i][0] += xv[i] * bA.x;
            acc[i][1] += xv[i] * bA.y;
            acc[i][2] += xv[i] * bB.x;
            acc[i][3] += xv[i] * bB.y;
        }
    }
    float* outp = g_st + (size_t)((b * NC + c) * NH + h) * HD * NS;
#pragma unroll
    for (int i = 0; i < 8; i++) {
        int p = pg * 8 + i;
        *(float2*)(outp + (size_t)p * NS + 2 * ng) = make_float2(acc[i][0], acc[i][1]);
        *(float2*)(outp + (size_t)p * NS + 64 + 2 * ng) = make_float2(acc[i][2], acc[i][3]);
    }
}

// ---------------- cross-chunk state scan ----------------
__global__ void __launch_bounds__(256) scan_kernel(const float* __restrict__ init_ssm,
                                                   float* __restrict__ final_out)
{
    const int seg = blockIdx.x;
    const int h = blockIdx.y, b = blockIdx.z;
    const int tid = threadIdx.x;
    const int e = seg * 1024 + tid * 4;
    const size_t base_bh = (size_t)(b * NH + h) * HD * NS;
    float4 S = *reinterpret_cast<const float4*>(init_ssm + base_bh + e);
    for (int c = 0; c < NC; c++) {
        float dec = expf(g_asum[(b * NC + c) * NH + h]);
        float* ptr = g_st + (size_t)((b * NC + c) * NH + h) * HD * NS + e;
        float4 cs = *reinterpret_cast<float4*>(ptr);
        *reinterpret_cast<float4*>(ptr) = S;
        S.x = dec * S.x + cs.x;
        S.y = dec * S.y + cs.y;
        S.z = dec * S.z + cs.z;
        S.w = dec * S.w + cs.w;
    }
    *reinterpret_cast<float4*>(final_out + base_bh + e) = S;
}

// ---------------- Y = (G∘L)@xdt + exp(Acs)*(C @ Sprev^T) + x*D ------------
// Phase1: shA = Sprev transposed [n=128][p pad 68], sC = C [l][132].
// Phase2: shA reused: sM [64][68] at 0, sxdt [64][68] at 64*68.
#define Y_SMEM ((128*68 + 64*132) * 4)
__global__ void __launch_bounds__(256) y_kernel(const float* __restrict__ A_log,
                                                const float* __restrict__ Dp)
{
    extern __shared__ float sm[];
    float* shA = sm;             // [128][68]
    float* sC  = sm + 128 * 68;  // [64][132]
    __shared__ float acs[64], sdt[64];
    const int h = blockIdx.x, c = blockIdx.y, b = blockIdx.z;
    const int tid = threadIdx.x;
    const int row0 = b * L_ + c * CH;
    if (tid < 64) sdt[tid] = g_dt[(size_t)(row0 + tid) * NH + h];
    __syncthreads();
    if (tid == 0) {
        float A = -expf(A_log[h]);
        float s = 0.f;
        for (int l = 0; l < 64; l++) { s += A * sdt[l]; acs[l] = s; }
    }
    __syncthreads();

    // load C [l][n] and Sprev transposed [n][p]
    const float* Sp = g_st + (size_t)((b * NC + c) * NH + h) * HD * NS;
    for (int i = tid; i < 64 * 32; i += 256) {
        int l = i >> 5, q = i & 31;
        *(float4*)(sC + l * 132 + q * 4) =
            *(const float4*)(g_Cm + (size_t)(row0 + l) * NS + q * 4);
    }
    for (int i = tid; i < 64 * 32; i += 256) {
        int p = i >> 5, q = i & 31;
        float4 v = *(const float4*)(Sp + (size_t)p * NS + q * 4);
        shA[(q * 4 + 0) * 68 + p] = v.x;
        shA[(q * 4 + 1) * 68 + p] = v.y;
        shA[(q * 4 + 2) * 68 + p] = v.z;
        shA[(q * 4 + 3) * 68 + p] = v.w;
    }
    __syncthreads();

    const int l = tid >> 2;
    const int p0 = (tid & 3) * 16;
    float acc[16];
#pragma unroll
    for (int j = 0; j < 16; j++) acc[j] = 0.f;

    // phase 1: Y_off[l][p] = sum_n C[l][n] * S^T[n][p]
    for (int nn = 0; nn < 128; nn++) {
        float cv = sC[l * 132 + nn];
        const float* sr = shA + nn * 68 + p0;
        float4 s0 = *(const float4*)(sr);
        float4 s1 = *(const float4*)(sr + 4);
        float4 s2 = *(const float4*)(sr + 8);
        float4 s3 = *(const float4*)(sr + 12);
        acc[0]  += cv * s0.x;  acc[1]  += cv * s0.y;  acc[2]  += cv * s0.z;  acc[3]  += cv * s0.w;
        acc[4]  += cv * s1.x;  acc[5]  += cv * s1.y;  acc[6]  += cv * s1.z;  acc[7]  += cv * s1.w;
        acc[8]  += cv * s2.x;  acc[9]  += cv * s2.y;  acc[10] += cv * s2.z;  acc[11] += cv * s2.w;
        acc[12] += cv * s3.x;  acc[13] += cv * s3.y;  acc[14] += cv * s3.z;  acc[15] += cv * s3.w;
    }
    float eAl = expf(acs[l]);
#pragma unroll
    for (int j = 0; j < 16; j++) acc[j] *= eAl;
    __syncthreads();   // done reading shA as S^T

    // phase 2: build sM = G*exp(acs[r]-acs[s]) masked, sxdt = x*dt [s][p]
    const float* Gp = g_G + (size_t)(b * NC + c) * (CH * CH);
    for (int i = tid; i < 64 * 64; i += 256) {
        int r = i >> 6, s = i & 63;
        shA[r * 68 + s] = (s <= r) ? Gp[r * 64 + s] * expf(acs[r] - acs[s]) : 0.f;
    }
    float* sxdt = shA + 64 * 68;
    for (int i = tid; i < 64 * 16; i += 256) {
        int s = i >> 4, q = i & 15;
        float4 v = *(const float4*)(g_x + (size_t)(row0 + s) * NI + h * HD + q * 4);
        float d = sdt[s];
        *(float4*)(sxdt + s * 68 + q * 4) = make_float4(v.x * d, v.y * d, v.z * d, v.w * d);
    }
    __syncthreads();

    for (int s = 0; s < 64; s++) {
        float gv = shA[l * 68 + s];
        const float* xr = sxdt + s * 68 + p0;
        float4 x0 = *(const float4*)(xr);
        float4 x1 = *(const float4*)(xr + 4);
        float4 x2 = *(const float4*)(xr + 8);
        float4 x3 = *(const float4*)(xr + 12);
        acc[0]  += gv * x0.x;  acc[1]  += gv * x0.y;  acc[2]  += gv * x0.z;  acc[3]  += gv * x0.w;
        acc[4]  += gv * x1.x;  acc[5]  += gv * x1.y;  acc[6]  += gv * x1.z;  acc[7]  += gv * x1.w;
        acc[8]  += gv * x2.x;  acc[9]  += gv * x2.y;  acc[10] += gv * x2.z;  acc[11] += gv * x2.w;
        acc[12] += gv * x3.x;  acc[13] += gv * x3.y;  acc[14] += gv * x3.z;  acc[15] += gv * x3.w;
    }

    float Dv = Dp[h];
    float* yrow = g_yin + (size_t)(row0 + l) * NI + h * HD + p0;
    const float* xrow = g_x + (size_t)(row0 + l) * NI + h * HD + p0;
#pragma unroll
    for (int j4 = 0; j4 < 4; j4++) {
        float4 xv = *(const float4*)(xrow + j4 * 4);
        float4 o = make_float4(acc[j4*4+0] + xv.x * Dv, acc[j4*4+1] + xv.y * Dv,
                               acc[j4*4+2] + xv.z * Dv, acc[j4*4+3] + xv.w * Dv);
        *(float4*)(yrow + j4 * 4) = o;
    }
}

// ------ gate with silu(z), RMSNorm, * norm_w; emit bf16 hi/lo directly ------
__global__ void __launch_bounds__(256) gate_rms_kernel(const float* __restrict__ norm_w) {
    const int row = blockIdx.x;
    const int tid = threadIdx.x;
    const float* zrow = g_zx + (size_t)row * DIN;
    const float* yrow = g_yin + (size_t)row * NI;
    float v[8];
    float ss = 0.f;
#pragma unroll
    for (int i = 0; i < 8; i++) {
        int idx = tid + i * 256;
        float z = zrow[idx];
        float val = yrow[idx] * siluf(z);
        v[i] = val;
        ss += val * val;
    }
    __shared__ float red[256];
    red[tid] = ss;
    __syncthreads();
    for (int s = 128; s > 0; s >>= 1) {
        if (tid < s) red[tid] += red[tid + s];
        __syncthreads();
    }
    float scale = rsqrtf(red[0] / (float)NI + 1e-5f);
#pragma unroll
    for (int i = 0; i < 8; i++) {
        int idx = tid + i * 256;
        float o = v[i] * scale * norm_w[idx];
        __nv_bfloat16 h = __float2bfloat16_rn(o);
        __nv_bfloat16 lo = __float2bfloat16_rn(o - __bfloat162float(h));
        g_ynb_hi[(size_t)row * NI + idx] = h;
        g_ynb_lo[(size_t)row * NI + idx] = lo;
    }
}

// ---------------- launch ----------------
template <typename T>
static T* symaddr(const void* sym) {
    void* p = nullptr;
    cudaGetSymbolAddress(&p, sym);
    return (T*)p;
}

extern "C" void kernel_launch(void* const* d_in, const int* in_sizes, int n_in,
                              void* d_out, int out_size)
{
    const float* u         = (const float*)d_in[0];
    const float* init_conv = (const float*)d_in[1];
    const float* init_ssm  = (const float*)d_in[2];
    const float* w_in      = (const float*)d_in[3];
    const float* conv_w    = (const float*)d_in[4];
    const float* conv_b    = (const float*)d_in[5];
    const float* dt_bias   = (const float*)d_in[6];
    const float* A_log     = (const float*)d_in[7];
    const float* Dp        = (const float*)d_in[8];
    const float* norm_w    = (const float*)d_in[9];
    const float* w_out     = (const float*)d_in[10];

    float* out       = (float*)d_out;
    float* out_y     = out;
    float* out_conv  = out + (size_t)ROWS * E_;
    float* out_final = out_conv + (size_t)B_ * CD * NCONV;

    float* pzx = symaddr<float>(g_zx);
    __nv_bfloat16* p_u_hi  = symaddr<__nv_bfloat16>(g_u_hi);
    __nv_bfloat16* p_u_lo  = symaddr<__nv_bfloat16>(g_u_lo);
    __nv_bfloat16* p_win_hi  = symaddr<__nv_bfloat16>(g_win_hi);
    __nv_bfloat16* p_win_lo  = symaddr<__nv_bfloat16>(g_win_lo);
    __nv_bfloat16* p_wout_hi = symaddr<__nv_bfloat16>(g_wout_hi);
    __nv_bfloat16* p_wout_lo = symaddr<__nv_bfloat16>(g_wout_lo);
    __nv_bfloat16* p_yn_hi = symaddr<__nv_bfloat16>(g_ynb_hi);
    __nv_bfloat16* p_yn_lo = symaddr<__nv_bfloat16>(g_ynb_lo);

    cudaFuncSetAttribute(gemm_bf16, cudaFuncAttributeMaxDynamicSharedMemorySize, GM_SMEM);
    cudaFuncSetAttribute(states_kernel, cudaFuncAttributeMaxDynamicSharedMemorySize, STATES_SMEM);
    cudaFuncSetAttribute(y_kernel, cudaFuncAttributeMaxDynamicSharedMemorySize, Y_SMEM);

    // 0) operand conversions to bf16 hi/lo
    cvt_hilo_kernel<<<(ROWS * E_ / 4 + 511) / 512, 512>>>(u, p_u_hi, p_u_lo, ROWS * E_);
    cvt_win_kernel<<<(E_ * NPAD / 4 + 511) / 512, 512>>>(w_in);
    cvt_hilo_kernel<<<(NI * E_ / 4 + 511) / 512, 512>>>(w_out, p_wout_hi, p_wout_lo, NI * E_);

    // 1) in-projection
    gemm_bf16<<<dim3(NPAD / 128, ROWS / 256), 512, GM_SMEM>>>(
        p_u_hi, p_u_lo, p_win_hi, p_win_lo, pzx, ROWS, DIN, E_, NPAD);
    // 2) dt
    dt_kernel<<<(ROWS * NH + 255) / 256, 256>>>(dt_bias);
    // 3) conv + silu + split
    conv_kernel<<<dim3((CD + 255) / 256, L_ / 8, B_), 256>>>(init_conv, conv_w, conv_b);
    // 4) new_conv_state output
    convstate_kernel<<<(B_ * CD * NCONV + 255) / 256, 256>>>(out_conv);
    // 5) per-chunk Gram matrix
    gmat_kernel<<<B_ * NC, 256>>>();
    // 6) per-chunk states
    states_kernel<<<dim3(NH, NC, B_), 256, STATES_SMEM>>>(A_log);
    // 7) cross-chunk scan
    scan_kernel<<<dim3(8, NH, B_), 256>>>(init_ssm, out_final);
    // 8) Y
    y_kernel<<<dim3(NH, NC, B_), 256, Y_SMEM>>>(A_log, Dp);
    // 9) gate + rmsnorm
    gate_rms_kernel<<<ROWS, 256>>>(norm_w);
    // 10) out-projection
    gemm_bf16<<<dim3(E_ / 128, ROWS / 256), 512, GM_SMEM>>>(
        p_yn_hi, p_yn_lo, p_wout_hi, p_wout_lo, out_y, ROWS, E_, NI, E_);
}